// round 14
// baseline (speedup 1.0000x reference)
#include <cuda_runtime.h>
#include <cuda_fp16.h>
#include <mma.h>
#include <math.h>
#include <stdint.h>

using namespace nvcuda;

// ---------------- problem dims ----------------
#define HDIM 256
#define GDIM 768
#define EDIM 200
#define NW 4096
#define TWSTEPS 32
#define NS 256
#define TSSTEPS 16
#define NR 16
#define TRSTEPS 16
#define MW (NW * TWSTEPS)
#define KPAD 224
#define KP4 (KPAD / 4)

typedef unsigned long long ull;
typedef __half h16;

// ---------------- scratch ----------------
__device__ __align__(16) h16 g_GXw[(size_t)MW * GDIM];   // fp16 word input gates
__device__ float g_GXs[(size_t)NS * TSSTEPS * GDIM];
__device__ float g_GXr[(size_t)NR * TRSTEPS * GDIM];
__device__ float g_HsA[NS * HDIM], g_HsB[NS * HDIM];
__device__ float g_HrA[NR * HDIM], g_HrB[NR * HDIM];
__device__ __align__(16) h16 g_Xh[(size_t)MW * KPAD];
__device__ __align__(16) h16 g_WihH[GDIM * KPAD];
__device__ __align__(16) h16 g_WhhH[GDIM * HDIM];
__device__ __align__(16) h16 g_WsH [GDIM * HDIM];
__device__ __align__(16) h16 g_WshhH[GDIM * HDIM];
__device__ __align__(16) h16 g_WrhhH[GDIM * HDIM];
__device__ __align__(16) h16 g_SHiB[NW * HDIM];

// ---------------- helpers ----------------
__device__ __forceinline__ float sigmoid_f(float x) { return 1.f / (1.f + expf(-x)); }
__device__ __forceinline__ ull pack2(float lo, float hi) {
    ull r; asm("mov.b64 %0, {%1, %2};" : "=l"(r) : "f"(lo), "f"(hi)); return r;
}
__device__ __forceinline__ ull dup2(float v) { return pack2(v, v); }
__device__ __forceinline__ void ffma2(ull& d, ull a, ull b) {
    asm("fma.rn.f32x2 %0, %1, %2, %3;" : "=l"(d) : "l"(a), "l"(b), "l"(d));
}
__device__ __forceinline__ float2 unpack2(ull v) {
    float2 f; asm("mov.b64 {%0, %1}, %2;" : "=f"(f.x), "=f"(f.y) : "l"(v)); return f;
}
__device__ __forceinline__ void cp16(uint32_t s, const void* g) {
    asm volatile("cp.async.cg.shared.global [%0], [%1], 16;" :: "r"(s), "l"(g));
}
#define CP_COMMIT() asm volatile("cp.async.commit_group;" ::: "memory")
#define CP_WAIT(n)  asm volatile("cp.async.wait_group %0;" :: "n"(n) : "memory")

__device__ __forceinline__ void ld_h4(float* o, const h16* p) {
    ull v = *reinterpret_cast<const ull*>(p);
    const h16* q = reinterpret_cast<const h16*>(&v);
    o[0] = __half2float(q[0]); o[1] = __half2float(q[1]);
    o[2] = __half2float(q[2]); o[3] = __half2float(q[3]);
}

// ---------------- prep kernels ----------------
__global__ void split_w_single(const float* __restrict__ src, h16* __restrict__ dst,
                               int rows, int cs, int cd)
{
    int i = blockIdx.x * blockDim.x + threadIdx.x;
    if (i >= rows * cd) return;
    int r = i / cd, c = i - r * cd;
    float v = (c < cs) ? src[(size_t)r * cs + c] : 0.f;
    dst[i] = __float2half_rn(v);
}

__global__ void split_w_quad(const float* s0, h16* d0, const float* s1, h16* d1,
                             const float* s2, h16* d2, const float* s3, h16* d3,
                             int n4)
{
    int i = blockIdx.x * blockDim.x + threadIdx.x;
    int mat = i / n4;
    int off = (i - mat * n4) * 4;
    if (mat >= 4) return;
    const float* s = (mat == 0) ? s0 : (mat == 1) ? s1 : (mat == 2) ? s2 : s3;
    h16* d = (mat == 0) ? d0 : (mat == 1) ? d1 : (mat == 2) ? d2 : d3;
    float4 v = *reinterpret_cast<const float4*>(s + off);
    h16 hb[4];
    hb[0] = __float2half_rn(v.x); hb[1] = __float2half_rn(v.y);
    hb[2] = __float2half_rn(v.z); hb[3] = __float2half_rn(v.w);
    *reinterpret_cast<ull*>(d + off) = *reinterpret_cast<ull*>(hb);
}

__global__ void gather_h16_kernel(const int* __restrict__ idx, const float* __restrict__ emb,
                                  h16* __restrict__ hi)
{
    size_t id = (size_t)blockIdx.x * blockDim.x + threadIdx.x;
    if (id >= (size_t)MW * KP4) return;
    int row = (int)(id / KP4);
    int c4 = (int)(id - (size_t)row * KP4) * 4;
    float4 v = make_float4(0.f, 0.f, 0.f, 0.f);
    if (c4 < EDIM)
        v = *reinterpret_cast<const float4*>(emb + (size_t)idx[row] * EDIM + c4);
    h16 hb[4];
    hb[0] = __float2half_rn(v.x); hb[1] = __float2half_rn(v.y);
    hb[2] = __float2half_rn(v.z); hb[3] = __float2half_rn(v.w);
    *reinterpret_cast<ull*>(hi + (size_t)row * KPAD + c4) = *reinterpret_cast<ull*>(hb);
}

// ---------------- wmma fp16 GEMM: C = A@W^T + bias (OutT = float or h16) ----
#define LDT2 40
#define TBY (128 * LDT2 * 2)
#define GEMM_BUF (2 * TBY)

template <typename OutT>
__global__ __launch_bounds__(256, 2)
void gemm_wmma2(const h16* __restrict__ Ahp, const h16* __restrict__ Whp,
                const float* __restrict__ bias, OutT* __restrict__ C,
                int K, int N)
{
    extern __shared__ __align__(128) char sm[];
    const uint32_t sbase = (uint32_t)__cvta_generic_to_shared(sm);
    float* scratch = reinterpret_cast<float*>(sm);

    const int tid = threadIdx.x;
    const int wid = tid >> 5;
    const int m0 = blockIdx.y * 128, n0 = blockIdx.x * 128;
    const int wm = wid & 3, wn = wid >> 2;

    const int lr = tid >> 1;
    const int lq = (tid & 1) * 16;

    const h16* gA = Ahp + (size_t)(m0 + lr) * K + lq;
    const h16* gB = Whp + (size_t)(n0 + lr) * K + lq;
    const uint32_t srow = lr * LDT2 * 2 + lq * 2;

    const int ntile = K / 32;

    wmma::fragment<wmma::accumulator, 16, 16, 16, float> cf[2][4];
#pragma unroll
    for (int i = 0; i < 2; i++)
#pragma unroll
        for (int j = 0; j < 4; j++) wmma::fill_fragment(cf[i][j], 0.0f);

    auto issue = [&](int it, int b) {
        const int kk = it * 32;
        uint32_t base = sbase + b * GEMM_BUF;
        cp16(base + srow,            gA + kk);
        cp16(base + srow + 16,       gA + kk + 8);
        cp16(base + TBY + srow,      gB + kk);
        cp16(base + TBY + srow + 16, gB + kk + 8);
    };

    issue(0, 0); CP_COMMIT();

    for (int it = 0; it < ntile; it++) {
        const int b = it & 1;
        if (it + 1 < ntile) { issue(it + 1, b ^ 1); CP_COMMIT(); CP_WAIT(1); }
        else                { CP_WAIT(0); }
        __syncthreads();

        const h16* tA = reinterpret_cast<const h16*>(sm + b * GEMM_BUF);
        const h16* tB = tA + 128 * LDT2;

#pragma unroll
        for (int ks = 0; ks < 32; ks += 16) {
            wmma::fragment<wmma::matrix_a, 16, 16, 16, h16, wmma::row_major> ah[2];
            wmma::fragment<wmma::matrix_b, 16, 16, 16, h16, wmma::col_major> bh[4];
#pragma unroll
            for (int i = 0; i < 2; i++)
                wmma::load_matrix_sync(ah[i], tA + (wm * 32 + i * 16) * LDT2 + ks, LDT2);
#pragma unroll
            for (int j = 0; j < 4; j++)
                wmma::load_matrix_sync(bh[j], tB + (wn * 64 + j * 16) * LDT2 + ks, LDT2);
#pragma unroll
            for (int i = 0; i < 2; i++)
#pragma unroll
                for (int j = 0; j < 4; j++)
                    wmma::mma_sync(cf[i][j], ah[i], bh[j], cf[i][j]);
        }
        __syncthreads();
    }

#pragma unroll
    for (int i = 0; i < 2; i++)
#pragma unroll
        for (int j = 0; j < 4; j++)
            wmma::store_matrix_sync(&scratch[(wm * 32 + i * 16) * 128 + wn * 64 + j * 16],
                                    cf[i][j], 128, wmma::mem_row_major);
    __syncthreads();

#pragma unroll
    for (int itx = 0; itx < 16; itx++) {
        int idx4 = tid + itx * 256;
        int r = idx4 >> 5;
        int c4 = (idx4 & 31) * 4;
        float4 v = *reinterpret_cast<const float4*>(&scratch[r * 128 + c4]);
        float4 b = *reinterpret_cast<const float4*>(&bias[n0 + c4]);
        v.x += b.x; v.y += b.y; v.z += b.z; v.w += b.w;
        if constexpr (sizeof(OutT) == 4) {
            *reinterpret_cast<float4*>(&C[(size_t)(m0 + r) * N + n0 + c4]) = v;
        } else {
            h16 hb[4];
            hb[0] = __float2half_rn(v.x); hb[1] = __float2half_rn(v.y);
            hb[2] = __float2half_rn(v.z); hb[3] = __float2half_rn(v.w);
            *reinterpret_cast<ull*>(&C[(size_t)(m0 + r) * N + n0 + c4]) =
                *reinterpret_cast<ull*>(hb);
        }
    }
}

// ---------------- sequence-local word GRU: no cross-CTA deps -----------------
// CTA owns SEQR=16 sequences; h lives in smem for all 32 steps. W streamed
// from L2 in 16 double-buffered chunks per step. grid = 256 CTAs, occ 2.
#define SEQR 16
#define HLD 264                        // h smem stride (halfs); 528B = 33 units, cf-free
#define HBYTES (SEQR * HLD * 2)        // 8448
#define WCHK 24                        // W chunk stride (halfs); 48B = 3 units, cf-free
#define WCHB (GDIM * WCHK * 2)         // 36864 per buffer
#define SEQSMEM (HBYTES + 2 * WCHB)    // 82176

__global__ __launch_bounds__(256, 2)
void gru_word_seqloc(const h16* __restrict__ Whp, const float* __restrict__ bhh,
                     const h16* __restrict__ gx, h16* __restrict__ hfin)
{
    extern __shared__ __align__(128) char sm[];
    const uint32_t sbase = (uint32_t)__cvta_generic_to_shared(sm);
    h16* hA = reinterpret_cast<h16*>(sm);
    float* scratch = reinterpret_cast<float*>(sm + HBYTES);   // aliases W buffers

    const int tid = threadIdx.x;
    const int wid = tid >> 5;
    const int seq0 = blockIdx.x * SEQR;

    // ---- t = 0: h0 from gx only (h_{-1} = 0) ----
    for (int task = tid; task < SEQR * 64; task += 256) {
        int s = task >> 6;
        int c4 = (task & 63) * 4;
        const h16* gxp = gx + (size_t)(seq0 + s) * TWSTEPS * GDIM;
        float xr[4], xz[4], xn[4], br[4], bz[4], bn[4];
        ld_h4(xr, gxp + c4);
        ld_h4(xz, gxp + HDIM + c4);
        ld_h4(xn, gxp + 2 * HDIM + c4);
        *reinterpret_cast<float4*>(br) = *reinterpret_cast<const float4*>(bhh + c4);
        *reinterpret_cast<float4*>(bz) = *reinterpret_cast<const float4*>(bhh + HDIM + c4);
        *reinterpret_cast<float4*>(bn) = *reinterpret_cast<const float4*>(bhh + 2 * HDIM + c4);
        h16 hb[4];
#pragma unroll
        for (int u = 0; u < 4; u++) {
            float r = sigmoid_f(xr[u] + br[u]);
            float z = sigmoid_f(xz[u] + bz[u]);
            float n = tanhf(xn[u] + r * bn[u]);
            hb[u] = __float2half_rn((1.f - z) * n);
        }
        *reinterpret_cast<ull*>(hA + s * HLD + c4) = *reinterpret_cast<ull*>(hb);
    }
    __syncthreads();

    for (int t = 1; t < TWSTEPS; t++) {
        auto issue = [&](int kt, int b) {
            const int kk = kt * 16;
            uint32_t base = sbase + HBYTES + b * WCHB;
#pragma unroll
            for (int rep = 0; rep < 6; rep++) {
                int task = tid + rep * 256;     // 1536 tasks: 768 rows x 2
                int row = task >> 1;
                int q = (task & 1) * 8;
                cp16(base + row * (WCHK * 2) + q * 2,
                     Whp + (size_t)row * HDIM + kk + q);
            }
        };

        wmma::fragment<wmma::accumulator, 16, 16, 16, float> cf[6];
#pragma unroll
        for (int j = 0; j < 6; j++) wmma::fill_fragment(cf[j], 0.0f);

        issue(0, 0); CP_COMMIT();

        for (int kt = 0; kt < 16; kt++) {
            const int b = kt & 1;
            if (kt + 1 < 16) { issue(kt + 1, b ^ 1); CP_COMMIT(); CP_WAIT(1); }
            else             { CP_WAIT(0); }
            __syncthreads();

            wmma::fragment<wmma::matrix_a, 16, 16, 16, h16, wmma::row_major> ah;
            wmma::load_matrix_sync(ah, hA + kt * 16, HLD);
            const h16* wb = reinterpret_cast<const h16*>(sm + HBYTES + b * WCHB);
#pragma unroll
            for (int j = 0; j < 6; j++) {
                wmma::fragment<wmma::matrix_b, 16, 16, 16, h16, wmma::col_major> bh;
                wmma::load_matrix_sync(bh, wb + (wid * 96 + j * 16) * WCHK, WCHK);
                wmma::mma_sync(cf[j], ah, bh, cf[j]);
            }
            __syncthreads();
        }

        // gates -> scratch [16][768] (aliases W buffers; all consumed)
#pragma unroll
        for (int j = 0; j < 6; j++)
            wmma::store_matrix_sync(&scratch[wid * 96 + j * 16], cf[j], GDIM,
                                    wmma::mem_row_major);
        __syncthreads();

        // GRU update in-place on hA
        for (int task = tid; task < SEQR * 64; task += 256) {
            int s = task >> 6;
            int c4 = (task & 63) * 4;
            const float* srow = &scratch[s * GDIM];
            float gr[4], gz[4], gn[4], br[4], bz[4], bn[4], xr[4], xz[4], xn[4], hh[4];
            *reinterpret_cast<float4*>(gr) = *reinterpret_cast<const float4*>(srow + c4);
            *reinterpret_cast<float4*>(gz) = *reinterpret_cast<const float4*>(srow + HDIM + c4);
            *reinterpret_cast<float4*>(gn) = *reinterpret_cast<const float4*>(srow + 2 * HDIM + c4);
            *reinterpret_cast<float4*>(br) = *reinterpret_cast<const float4*>(bhh + c4);
            *reinterpret_cast<float4*>(bz) = *reinterpret_cast<const float4*>(bhh + HDIM + c4);
            *reinterpret_cast<float4*>(bn) = *reinterpret_cast<const float4*>(bhh + 2 * HDIM + c4);
            const h16* gxp = gx + ((size_t)(seq0 + s) * TWSTEPS + t) * GDIM;
            ld_h4(xr, gxp + c4);
            ld_h4(xz, gxp + HDIM + c4);
            ld_h4(xn, gxp + 2 * HDIM + c4);
            ld_h4(hh, hA + s * HLD + c4);
            h16 hb[4];
#pragma unroll
            for (int u = 0; u < 4; u++) {
                float rr = sigmoid_f(xr[u] + gr[u] + br[u]);
                float zz = sigmoid_f(xz[u] + gz[u] + bz[u]);
                float nv = tanhf(xn[u] + rr * (gn[u] + bn[u]));
                float h = (1.f - zz) * nv + zz * hh[u];
                hb[u] = __float2half_rn(h);
            }
            *reinterpret_cast<ull*>(hA + s * HLD + c4) = *reinterpret_cast<ull*>(hb);
        }
        __syncthreads();
    }

    // write final h
    for (int task = tid; task < SEQR * 64; task += 256) {
        int s = task >> 6;
        int c4 = (task & 63) * 4;
        *reinterpret_cast<ull*>(hfin + (size_t)(seq0 + s) * HDIM + c4) =
            *reinterpret_cast<const ull*>(hA + s * HLD + c4);
    }
}

// ---------------- t=0 GRU step (fp32, sentence/review tails) ----------------
__global__ void gru_init_plain(const float* __restrict__ gx, const float* __restrict__ bhh,
                               float* __restrict__ hout, int Mseq, int T)
{
    int i = blockIdx.x * blockDim.x + threadIdx.x;
    if (i >= Mseq * HDIM) return;
    int seq = i >> 8, j = i & 255;
    const float* g = gx + (size_t)seq * T * GDIM;
    float r = sigmoid_f(g[j] + bhh[j]);
    float z = sigmoid_f(g[j + HDIM] + bhh[j + HDIM]);
    float n = tanhf(g[j + 2 * HDIM] + r * bhh[j + 2 * HDIM]);
    hout[i] = (1.f - z) * n;
}

// ---------------- fused multi-step GRU tail ----------------------------------
template <int NSEQ>
__global__ __launch_bounds__(256)
void gru_tail_fused(const float* __restrict__ h0, const h16* __restrict__ W16,
                    const float* __restrict__ bhh, const float* __restrict__ gx,
                    int T, float* __restrict__ hfinal)
{
    __shared__ float hs[HDIM][NSEQ];
    const int tid = threadIdx.x;
    const int seq0 = blockIdx.x * NSEQ;

    for (int i = tid; i < NSEQ * HDIM; i += 256) {
        int s = i / HDIM, k = i - s * HDIM;
        hs[k][s] = h0[(size_t)(seq0 + s) * HDIM + k];
    }
    __syncthreads();

    const int j = tid;
    const h16* wr = W16 + (size_t)j * HDIM;
    const h16* wz = W16 + (size_t)(HDIM + j) * HDIM;
    const h16* wn_ = W16 + (size_t)(2 * HDIM + j) * HDIM;
    const float br = bhh[j], bz = bhh[HDIM + j], bn = bhh[2 * HDIM + j];

    for (int t = 1; t < T; t++) {
        float ar[NSEQ], az[NSEQ], an[NSEQ];
#pragma unroll
        for (int s = 0; s < NSEQ; s++) { ar[s] = 0.f; az[s] = 0.f; an[s] = 0.f; }

#pragma unroll 4
        for (int k = 0; k < HDIM; k += 8) {
            uint4 vr = *reinterpret_cast<const uint4*>(wr + k);
            uint4 vz = *reinterpret_cast<const uint4*>(wz + k);
            uint4 vn = *reinterpret_cast<const uint4*>(wn_ + k);
            const h16* pr = reinterpret_cast<const h16*>(&vr);
            const h16* pz = reinterpret_cast<const h16*>(&vz);
            const h16* pn = reinterpret_cast<const h16*>(&vn);
#pragma unroll
            for (int u = 0; u < 8; u++) {
                float fr = __half2float(pr[u]);
                float fz = __half2float(pz[u]);
                float fn = __half2float(pn[u]);
#pragma unroll
                for (int s = 0; s < NSEQ; s++) {
                    float hv = hs[k + u][s];
                    ar[s] = fmaf(fr, hv, ar[s]);
                    az[s] = fmaf(fz, hv, az[s]);
                    an[s] = fmaf(fn, hv, an[s]);
                }
            }
        }
        __syncthreads();

        float hnew[NSEQ];
#pragma unroll
        for (int s = 0; s < NSEQ; s++) {
            const float* gxp = gx + ((size_t)(seq0 + s) * T + t) * GDIM;
            float r = sigmoid_f(gxp[j] + ar[s] + br);
            float z = sigmoid_f(gxp[HDIM + j] + az[s] + bz);
            float n = tanhf(gxp[2 * HDIM + j] + r * (an[s] + bn));
            hnew[s] = (1.f - z) * n + z * hs[j][s];
        }
#pragma unroll
        for (int s = 0; s < NSEQ; s++) hs[j][s] = hnew[s];
        __syncthreads();
    }

    for (int i = tid; i < NSEQ * HDIM; i += 256) {
        int s = i / HDIM, k = i - s * HDIM;
        hfinal[(size_t)(seq0 + s) * HDIM + k] = hs[k][s];
    }
}

// ---------------- fp32 SGEMM (review gx) ----------------
#define BM 128
#define BN 128
#define BK 8
__global__ __launch_bounds__(256, 2)
void sgemm_f32x2(const float* __restrict__ A, const float* __restrict__ W,
                 const float* __restrict__ bias, float* __restrict__ C,
                 int M, int K, int N)
{
    __shared__ float As[2][BK][BM];
    __shared__ float Bs[2][BK][BN];
    const int tid = threadIdx.x;
    const int m0 = blockIdx.y * BM;
    const int n0 = blockIdx.x * BN;
    const int a_m = tid & 127, a_kq = tid >> 7;
    const int b_n = tid >> 1,  b_kq = tid & 1;
    const bool a_valid = (m0 + a_m) < M;
    const float* Arow = A + (size_t)(a_valid ? (m0 + a_m) : 0) * K;
    const float* Brow = W + (size_t)(n0 + b_n) * K;
    const int tx = tid & 15, ty = tid >> 4;

    ull acc2[8][4];
#pragma unroll
    for (int i = 0; i < 8; i++)
#pragma unroll
        for (int j = 0; j < 4; j++) acc2[i][j] = 0ull;

    float4 av = make_float4(0.f, 0.f, 0.f, 0.f);
    if (a_valid) av = *reinterpret_cast<const float4*>(Arow + a_kq * 4);
    float4 bv = *reinterpret_cast<const float4*>(Brow + b_kq * 4);
    As[0][a_kq * 4 + 0][a_m] = av.x;  As[0][a_kq * 4 + 1][a_m] = av.y;
    As[0][a_kq * 4 + 2][a_m] = av.z;  As[0][a_kq * 4 + 3][a_m] = av.w;
    Bs[0][b_kq * 4 + 0][b_n] = bv.x;  Bs[0][b_kq * 4 + 1][b_n] = bv.y;
    Bs[0][b_kq * 4 + 2][b_n] = bv.z;  Bs[0][b_kq * 4 + 3][b_n] = bv.w;
    __syncthreads();

    int buf = 0;
    for (int kk = 0; kk < K; kk += BK) {
        const bool has_next = (kk + BK) < K;
        if (has_next) {
            if (a_valid) av = *reinterpret_cast<const float4*>(Arow + kk + BK + a_kq * 4);
            bv = *reinterpret_cast<const float4*>(Brow + kk + BK + b_kq * 4);
        }
#pragma unroll
        for (int k = 0; k < BK; k++) {
            float4 a0 = *reinterpret_cast<const float4*>(&As[buf][k][ty * 8]);
            float4 a1 = *reinterpret_cast<const float4*>(&As[buf][k][ty * 8 + 4]);
            ulonglong2 bq0 = *reinterpret_cast<const ulonglong2*>(&Bs[buf][k][tx * 8]);
            ulonglong2 bq1 = *reinterpret_cast<const ulonglong2*>(&Bs[buf][k][tx * 8 + 4]);
            ull bp[4] = {bq0.x, bq0.y, bq1.x, bq1.y};
            float a[8] = {a0.x, a0.y, a0.z, a0.w, a1.x, a1.y, a1.z, a1.w};
#pragma unroll
            for (int i = 0; i < 8; i++) {
                ull ad = dup2(a[i]);
#pragma unroll
                for (int j = 0; j < 4; j++) ffma2(acc2[i][j], ad, bp[j]);
            }
        }
        if (has_next) {
            int nb = buf ^ 1;
            As[nb][a_kq * 4 + 0][a_m] = av.x;  As[nb][a_kq * 4 + 1][a_m] = av.y;
            As[nb][a_kq * 4 + 2][a_m] = av.z;  As[nb][a_kq * 4 + 3][a_m] = av.w;
            Bs[nb][b_kq * 4 + 0][b_n] = bv.x;  Bs[nb][b_kq * 4 + 1][b_n] = bv.y;
            Bs[nb][b_kq * 4 + 2][b_n] = bv.z;  Bs[nb][b_kq * 4 + 3][b_n] = bv.w;
            __syncthreads();
            buf = nb;
        }
    }
#pragma unroll
    for (int i = 0; i < 8; i++) {
        int row = m0 + ty * 8 + i;
        if (row >= M) continue;
#pragma unroll
        for (int j = 0; j < 4; j++) {
            int col = n0 + tx * 8 + j * 2;
            float2 p = unpack2(acc2[i][j]);
            float2 bb = *reinterpret_cast<const float2*>(bias + col);
            float2 o; o.x = p.x + bb.x; o.y = p.y + bb.y;
            *reinterpret_cast<float2*>(C + (size_t)row * N + col) = o;
        }
    }
}

// ---------------- MLP ----------------
__global__ __launch_bounds__(128)
void mlp_kernel(const float* __restrict__ X,
                const float* __restrict__ W1, const float* __restrict__ b1,
                const float* __restrict__ W2, const float* __restrict__ b2,
                float* __restrict__ out)
{
    const int row = blockIdx.x;
    const int i = threadIdx.x;
    __shared__ float xs[HDIM];
    __shared__ float red[4];
    xs[i]       = X[(size_t)row * HDIM + i];
    xs[i + 128] = X[(size_t)row * HDIM + i + 128];
    __syncthreads();
    const float* w = W1 + (size_t)i * HDIM;
    float acc = b1[i];
#pragma unroll 8
    for (int k = 0; k < HDIM; k += 4) {
        float4 wv = *reinterpret_cast<const float4*>(w + k);
        acc = fmaf(wv.x, xs[k], acc);
        acc = fmaf(wv.y, xs[k + 1], acc);
        acc = fmaf(wv.z, xs[k + 2], acc);
        acc = fmaf(wv.w, xs[k + 3], acc);
    }
    const float scale = 1.0507009873554805f;
    const float alpha = 1.6732632423543772f;
    float s = scale * (acc > 0.f ? acc : alpha * (expf(acc) - 1.f));
    float v = s * W2[i];
#pragma unroll
    for (int off = 16; off > 0; off >>= 1)
        v += __shfl_down_sync(0xffffffffu, v, off);
    if ((i & 31) == 0) red[i >> 5] = v;
    __syncthreads();
    if (i == 0) out[row] = red[0] + red[1] + red[2] + red[3] + b2[0];
}

// ---------------- host orchestration ----------------
extern "C" void kernel_launch(void* const* d_in, const int* in_sizes, int n_in,
                              void* d_out, int out_size)
{
    (void)in_sizes; (void)n_in; (void)out_size;

    const int*   idx    = (const int*)  d_in[0];
    const float* emb    = (const float*)d_in[1];
    const float* w_Wih  = (const float*)d_in[2];
    const float* w_Whh  = (const float*)d_in[3];
    const float* w_bih  = (const float*)d_in[4];
    const float* w_bhh  = (const float*)d_in[5];
    const float* s_Wih  = (const float*)d_in[6];
    const float* s_Whh  = (const float*)d_in[7];
    const float* s_bih  = (const float*)d_in[8];
    const float* s_bhh  = (const float*)d_in[9];
    const float* r_Wih  = (const float*)d_in[10];
    const float* r_Whh  = (const float*)d_in[11];
    const float* r_bih  = (const float*)d_in[12];
    const float* r_bhh  = (const float*)d_in[13];
    const float* rfc_W1 = (const float*)d_in[14];
    const float* rfc_b1 = (const float*)d_in[15];
    const float* rfc_W2 = (const float*)d_in[16];
    const float* rfc_b2 = (const float*)d_in[17];
    const float* pfc_W1 = (const float*)d_in[18];
    const float* pfc_b1 = (const float*)d_in[19];
    const float* pfc_W2 = (const float*)d_in[20];
    const float* pfc_b2 = (const float*)d_in[21];
    float* out = (float*)d_out;

    float *GXs, *GXr, *HsA, *HsB, *HrA, *HrB;
    h16 *GXw, *Xh, *WihH, *WhhH, *WsH, *WshhH, *WrhhH, *SHiB;
    cudaGetSymbolAddress((void**)&GXw, g_GXw);
    cudaGetSymbolAddress((void**)&GXs, g_GXs);
    cudaGetSymbolAddress((void**)&GXr, g_GXr);
    cudaGetSymbolAddress((void**)&HsA, g_HsA);
    cudaGetSymbolAddress((void**)&HsB, g_HsB);
    cudaGetSymbolAddress((void**)&HrA, g_HrA);
    cudaGetSymbolAddress((void**)&HrB, g_HrB);
    cudaGetSymbolAddress((void**)&Xh, g_Xh);
    cudaGetSymbolAddress((void**)&WihH, g_WihH);
    cudaGetSymbolAddress((void**)&WhhH, g_WhhH);
    cudaGetSymbolAddress((void**)&WsH, g_WsH);
    cudaGetSymbolAddress((void**)&WshhH, g_WshhH);
    cudaGetSymbolAddress((void**)&WrhhH, g_WrhhH);
    cudaGetSymbolAddress((void**)&SHiB, g_SHiB);

    const int SMEM_GEMM = 65536;
    cudaFuncSetAttribute(gemm_wmma2<h16>, cudaFuncAttributeMaxDynamicSharedMemorySize, SMEM_GEMM);
    cudaFuncSetAttribute(gemm_wmma2<float>, cudaFuncAttributeMaxDynamicSharedMemorySize, SMEM_GEMM);
    cudaFuncSetAttribute(gru_word_seqloc, cudaFuncAttributeMaxDynamicSharedMemorySize, SEQSMEM);

    // ---- prep ----
    split_w_single<<<(GDIM * KPAD + 255) / 256, 256>>>(w_Wih, WihH, GDIM, EDIM, KPAD);
    {
        int n4 = GDIM * HDIM / 4;
        split_w_quad<<<(4 * n4 + 255) / 256, 256>>>(w_Whh, WhhH, s_Wih, WsH,
                                                    s_Whh, WshhH, r_Whh, WrhhH, n4);
    }
    gather_h16_kernel<<<(int)(((size_t)MW * KP4 + 255) / 256), 256>>>(idx, emb, Xh);

    // ---- word level: gx (fp16 out) ----
    gemm_wmma2<h16><<<dim3(GDIM / 128, MW / 128), 256, SMEM_GEMM>>>(Xh, WihH,
                                                                    w_bih, GXw, KPAD, GDIM);

    // ---- word GRU: sequence-local, one launch, no cross-CTA sync ----
    gru_word_seqloc<<<NW / SEQR, 256, SEQSMEM>>>(WhhH, w_bhh, GXw, SHiB);
    h16* sent_hi = SHiB;

    // ---- sentence level ----
    gemm_wmma2<float><<<dim3(GDIM / 128, (NS * TSSTEPS) / 128), 256, SMEM_GEMM>>>(
        sent_hi, WsH, s_bih, GXs, HDIM, GDIM);

    gru_init_plain<<<(NS * HDIM + 255) / 256, 256>>>(GXs, s_bhh, HsA, NS, TSSTEPS);
    gru_tail_fused<4><<<NS / 4, 256>>>(HsA, WshhH, s_bhh, GXs, TSSTEPS, HsB);
    const float* p_batch = HsB;

    // r_stars -> out[16 .. 272)
    mlp_kernel<<<NS, 128>>>(p_batch, rfc_W1, rfc_b1, rfc_W2, rfc_b2, out + NR);

    // ---- review level ----
    {
        dim3 grid(GDIM / BN, (NR * TRSTEPS + BM - 1) / BM);
        sgemm_f32x2<<<grid, 256>>>(p_batch, r_Wih, r_bih, GXr, NR * TRSTEPS, HDIM, GDIM);
    }
    gru_init_plain<<<(NR * HDIM + 255) / 256, 256>>>(GXr, r_bhh, HrA, NR, TRSTEPS);
    gru_tail_fused<1><<<NR, 256>>>(HrA, WrhhH, r_bhh, GXr, TRSTEPS, HrB);

    // b_stars -> out[0 .. 16)
    mlp_kernel<<<NR, 128>>>(HrB, pfc_W1, pfc_b1, pfc_W2, pfc_b2, out);
}

// round 15
// speedup vs baseline: 1.2945x; 1.2945x over previous
#include <cuda_runtime.h>
#include <cuda_fp16.h>
#include <mma.h>
#include <cooperative_groups.h>
#include <math.h>
#include <stdint.h>

using namespace nvcuda;
namespace cg = cooperative_groups;

// ---------------- problem dims ----------------
#define HDIM 256
#define GDIM 768
#define EDIM 200
#define NW 4096
#define TWSTEPS 32
#define NS 256
#define TSSTEPS 16
#define NR 16
#define TRSTEPS 16
#define MW (NW * TWSTEPS)
#define KPAD 224
#define KP4 (KPAD / 4)

typedef unsigned long long ull;
typedef __half h16;

// ---------------- scratch ----------------
__device__ __align__(16) h16 g_GXw[(size_t)MW * GDIM];   // fp16 word input gates
__device__ float g_GXs[(size_t)NS * TSSTEPS * GDIM];
__device__ float g_GXr[(size_t)NR * TRSTEPS * GDIM];
__device__ float g_HsA[NS * HDIM], g_HsB[NS * HDIM];
__device__ float g_HrA[NR * HDIM], g_HrB[NR * HDIM];
__device__ __align__(16) h16 g_Xh[(size_t)MW * KPAD];
__device__ __align__(16) h16 g_WihH[GDIM * KPAD];
__device__ __align__(16) h16 g_WhhH[GDIM * HDIM];
__device__ __align__(16) h16 g_WsH [GDIM * HDIM];
__device__ __align__(16) h16 g_WshhH[GDIM * HDIM];
__device__ __align__(16) h16 g_WrhhH[GDIM * HDIM];
__device__ __align__(16) h16 g_SHiA[NW * HDIM], g_SHiB[NW * HDIM];

// ---------------- helpers ----------------
__device__ __forceinline__ float sigmoid_f(float x) { return 1.f / (1.f + expf(-x)); }
__device__ __forceinline__ ull pack2(float lo, float hi) {
    ull r; asm("mov.b64 %0, {%1, %2};" : "=l"(r) : "f"(lo), "f"(hi)); return r;
}
__device__ __forceinline__ ull dup2(float v) { return pack2(v, v); }
__device__ __forceinline__ void ffma2(ull& d, ull a, ull b) {
    asm("fma.rn.f32x2 %0, %1, %2, %3;" : "=l"(d) : "l"(a), "l"(b), "l"(d));
}
__device__ __forceinline__ float2 unpack2(ull v) {
    float2 f; asm("mov.b64 {%0, %1}, %2;" : "=f"(f.x), "=f"(f.y) : "l"(v)); return f;
}
__device__ __forceinline__ void cp16(uint32_t s, const void* g) {
    asm volatile("cp.async.cg.shared.global [%0], [%1], 16;" :: "r"(s), "l"(g));
}
#define CP_COMMIT() asm volatile("cp.async.commit_group;" ::: "memory")
#define CP_WAIT(n)  asm volatile("cp.async.wait_group %0;" :: "n"(n) : "memory")

__device__ __forceinline__ void ld_h4(float* o, const h16* p) {
    ull v = *reinterpret_cast<const ull*>(p);
    const h16* q = reinterpret_cast<const h16*>(&v);
    o[0] = __half2float(q[0]); o[1] = __half2float(q[1]);
    o[2] = __half2float(q[2]); o[3] = __half2float(q[3]);
}

// ---------------- prep kernels ----------------
__global__ void split_w_single(const float* __restrict__ src, h16* __restrict__ dst,
                               int rows, int cs, int cd)
{
    int i = blockIdx.x * blockDim.x + threadIdx.x;
    if (i >= rows * cd) return;
    int r = i / cd, c = i - r * cd;
    float v = (c < cs) ? src[(size_t)r * cs + c] : 0.f;
    dst[i] = __float2half_rn(v);
}

__global__ void split_w_quad(const float* s0, h16* d0, const float* s1, h16* d1,
                             const float* s2, h16* d2, const float* s3, h16* d3,
                             int n4)
{
    int i = blockIdx.x * blockDim.x + threadIdx.x;
    int mat = i / n4;
    int off = (i - mat * n4) * 4;
    if (mat >= 4) return;
    const float* s = (mat == 0) ? s0 : (mat == 1) ? s1 : (mat == 2) ? s2 : s3;
    h16* d = (mat == 0) ? d0 : (mat == 1) ? d1 : (mat == 2) ? d2 : d3;
    float4 v = *reinterpret_cast<const float4*>(s + off);
    h16 hb[4];
    hb[0] = __float2half_rn(v.x); hb[1] = __float2half_rn(v.y);
    hb[2] = __float2half_rn(v.z); hb[3] = __float2half_rn(v.w);
    *reinterpret_cast<ull*>(d + off) = *reinterpret_cast<ull*>(hb);
}

__global__ void gather_h16_kernel(const int* __restrict__ idx, const float* __restrict__ emb,
                                  h16* __restrict__ hi)
{
    size_t id = (size_t)blockIdx.x * blockDim.x + threadIdx.x;
    if (id >= (size_t)MW * KP4) return;
    int row = (int)(id / KP4);
    int c4 = (int)(id - (size_t)row * KP4) * 4;
    float4 v = make_float4(0.f, 0.f, 0.f, 0.f);
    if (c4 < EDIM)
        v = *reinterpret_cast<const float4*>(emb + (size_t)idx[row] * EDIM + c4);
    h16 hb[4];
    hb[0] = __float2half_rn(v.x); hb[1] = __float2half_rn(v.y);
    hb[2] = __float2half_rn(v.z); hb[3] = __float2half_rn(v.w);
    *reinterpret_cast<ull*>(hi + (size_t)row * KPAD + c4) = *reinterpret_cast<ull*>(hb);
}

// ---------------- wmma fp16 GEMM: C = A@W^T + bias (3-stage pipeline) -------
#define LDT2 40
#define TBY (128 * LDT2 * 2)         // 10240B per matrix tile
#define GEMM_BUF (2 * TBY)           // per stage: A + B

template <typename OutT>
__global__ __launch_bounds__(256, 2)
void gemm_wmma2(const h16* __restrict__ Ahp, const h16* __restrict__ Whp,
                const float* __restrict__ bias, OutT* __restrict__ C,
                int K, int N)
{
    extern __shared__ __align__(128) char sm[];
    const uint32_t sbase = (uint32_t)__cvta_generic_to_shared(sm);
    float* scratch = reinterpret_cast<float*>(sm);

    const int tid = threadIdx.x;
    const int wid = tid >> 5;
    const int m0 = blockIdx.y * 128, n0 = blockIdx.x * 128;
    const int wm = wid & 3, wn = wid >> 2;

    const int lr = tid >> 1;
    const int lq = (tid & 1) * 16;

    const h16* gA = Ahp + (size_t)(m0 + lr) * K + lq;
    const h16* gB = Whp + (size_t)(n0 + lr) * K + lq;
    const uint32_t srow = lr * LDT2 * 2 + lq * 2;

    const int ntile = K / 32;

    wmma::fragment<wmma::accumulator, 16, 16, 16, float> cf[2][4];
#pragma unroll
    for (int i = 0; i < 2; i++)
#pragma unroll
        for (int j = 0; j < 4; j++) wmma::fill_fragment(cf[i][j], 0.0f);

    auto issue = [&](int it, int stg) {
        const int kk = it * 32;
        uint32_t base = sbase + stg * GEMM_BUF;
        cp16(base + srow,            gA + kk);
        cp16(base + srow + 16,       gA + kk + 8);
        cp16(base + TBY + srow,      gB + kk);
        cp16(base + TBY + srow + 16, gB + kk + 8);
    };

    issue(0, 0); CP_COMMIT();
    if (ntile > 1) { issue(1, 1); CP_COMMIT(); }

    for (int it = 0; it < ntile; it++) {
        if (it + 1 < ntile) { CP_WAIT(1); } else { CP_WAIT(0); }
        __syncthreads();
        if (it + 2 < ntile) { issue(it + 2, (it + 2) % 3); CP_COMMIT(); }

        const h16* tA = reinterpret_cast<const h16*>(sm + (it % 3) * GEMM_BUF);
        const h16* tB = tA + 128 * LDT2;

#pragma unroll
        for (int ks = 0; ks < 32; ks += 16) {
            wmma::fragment<wmma::matrix_a, 16, 16, 16, h16, wmma::row_major> ah[2];
            wmma::fragment<wmma::matrix_b, 16, 16, 16, h16, wmma::col_major> bh[4];
#pragma unroll
            for (int i = 0; i < 2; i++)
                wmma::load_matrix_sync(ah[i], tA + (wm * 32 + i * 16) * LDT2 + ks, LDT2);
#pragma unroll
            for (int j = 0; j < 4; j++)
                wmma::load_matrix_sync(bh[j], tB + (wn * 64 + j * 16) * LDT2 + ks, LDT2);
#pragma unroll
            for (int i = 0; i < 2; i++)
#pragma unroll
                for (int j = 0; j < 4; j++)
                    wmma::mma_sync(cf[i][j], ah[i], bh[j], cf[i][j]);
        }
    }
    __syncthreads();   // all compute done before scratch (aliases stage buffers)

#pragma unroll
    for (int i = 0; i < 2; i++)
#pragma unroll
        for (int j = 0; j < 4; j++)
            wmma::store_matrix_sync(&scratch[(wm * 32 + i * 16) * 128 + wn * 64 + j * 16],
                                    cf[i][j], 128, wmma::mem_row_major);
    __syncthreads();

#pragma unroll
    for (int itx = 0; itx < 16; itx++) {
        int idx4 = tid + itx * 256;
        int r = idx4 >> 5;
        int c4 = (idx4 & 31) * 4;
        float4 v = *reinterpret_cast<const float4*>(&scratch[r * 128 + c4]);
        float4 b = *reinterpret_cast<const float4*>(&bias[n0 + c4]);
        v.x += b.x; v.y += b.y; v.z += b.z; v.w += b.w;
        if constexpr (sizeof(OutT) == 4) {
            *reinterpret_cast<float4*>(&C[(size_t)(m0 + r) * N + n0 + c4]) = v;
        } else {
            h16 hb[4];
            hb[0] = __float2half_rn(v.x); hb[1] = __float2half_rn(v.y);
            hb[2] = __float2half_rn(v.z); hb[3] = __float2half_rn(v.w);
            *reinterpret_cast<ull*>(&C[(size_t)(m0 + r) * N + n0 + c4]) =
                *reinterpret_cast<ull*>(hb);
        }
    }
}

// ---------------- persistent cooperative word-recurrent loop -----------------
// CTA = 128 rows x 32 h-cols (96 gate rows). W tile smem-resident (loaded once).
// grid (8, 32) = 256 CTAs, occ 2. A staging: 3-stage pipeline, 1 sync/chunk.
#define WROWS 96
#define WLD 264                        // 528B stride, 33 mod 8 = 1 -> conflict-free
#define WBYTES (WROWS * WLD * 2)       // 50688
#define ABUF (128 * LDT2 * 2)          // 10240 per A buffer
#define PSMEM (WBYTES + 3 * ABUF)      // 50688 + 30720 = 81408 (>= 24576 scratch)

__global__ __launch_bounds__(256, 2)
void gru_word_persistent(h16* __restrict__ sA, h16* __restrict__ sB,
                         const h16* __restrict__ Whp,
                         const float* __restrict__ bhh, const h16* __restrict__ gx)
{
    extern __shared__ __align__(128) char sm[];
    const uint32_t sbase = (uint32_t)__cvta_generic_to_shared(sm);
    const h16* Wsm = reinterpret_cast<const h16*>(sm);
    float* scratch = reinterpret_cast<float*>(sm + WBYTES);   // 64x96 fp32 (24KB)

    cg::grid_group grid = cg::this_grid();

    const int tid = threadIdx.x;
    const int wid = tid >> 5;
    const int n0 = blockIdx.x * 32;
    const int m0 = blockIdx.y * 128;
    const int wm = wid & 3;
    const int wn = wid >> 2;

    // ---- prologue: load W tile (96 gate-rows x 256 K) once ----
    for (int task = tid; task < WROWS * 32; task += 256) {
        int rt = task >> 5;
        int q = task & 31;
        int gate = rt >> 5, col = rt & 31;
        size_t srcoff = (size_t)(gate * HDIM + n0 + col) * HDIM + q * 8;
        cp16(sbase + rt * (WLD * 2) + q * 16, Whp + srcoff);
    }
    CP_COMMIT(); CP_WAIT(0);
    __syncthreads();

    const int lr = tid >> 1;
    const int lq = (tid & 1) * 16;
    const uint32_t arow = lr * (LDT2 * 2) + lq * 2;

    for (int t = 1; t < TWSTEPS; t++) {
        const int cur = (t - 1) & 1;
        const h16* Hhi  = cur ? sB : sA;
        h16*       Hout = cur ? sA : sB;

        const h16* gAh = Hhi + (size_t)(m0 + lr) * HDIM + lq;

        auto issue = [&](int it, int stg) {
            const int kk = it * 32;
            uint32_t base = sbase + WBYTES + stg * ABUF;
            cp16(base + arow,      gAh + kk);
            cp16(base + arow + 16, gAh + kk + 8);
        };

        wmma::fragment<wmma::accumulator, 16, 16, 16, float> cf[2][3];
#pragma unroll
        for (int i = 0; i < 2; i++)
#pragma unroll
            for (int j = 0; j < 3; j++) wmma::fill_fragment(cf[i][j], 0.0f);

        issue(0, 0); CP_COMMIT();
        issue(1, 1); CP_COMMIT();

        const int ntile = HDIM / 32;     // 8
        for (int it = 0; it < ntile; it++) {
            if (it + 1 < ntile) { CP_WAIT(1); } else { CP_WAIT(0); }
            __syncthreads();
            if (it + 2 < ntile) { issue(it + 2, (it + 2) % 3); CP_COMMIT(); }

            const h16* tA = reinterpret_cast<const h16*>(sm + WBYTES + (it % 3) * ABUF);
            const int kk = it * 32;

#pragma unroll
            for (int ks = 0; ks < 32; ks += 16) {
                wmma::fragment<wmma::matrix_a, 16, 16, 16, h16, wmma::row_major> ah0, ah1;
                wmma::load_matrix_sync(ah0, tA + (wm * 32) * LDT2 + ks, LDT2);
                wmma::load_matrix_sync(ah1, tA + (wm * 32 + 16) * LDT2 + ks, LDT2);
#pragma unroll
                for (int j = 0; j < 3; j++) {
                    wmma::fragment<wmma::matrix_b, 16, 16, 16, h16, wmma::col_major> bh;
                    wmma::load_matrix_sync(bh, Wsm + (wn * 48 + j * 16) * WLD + kk + ks, WLD);
                    wmma::mma_sync(cf[0][j], ah0, bh, cf[0][j]);
                    wmma::mma_sync(cf[1][j], ah1, bh, cf[1][j]);
                }
            }
        }
        __syncthreads();   // compute done before scratch (aliases A buffers)

        // ---- epilogue in 2 row-passes ----
#pragma unroll
        for (int p = 0; p < 2; p++) {
            __syncthreads();
            if ((wm >> 1) == p) {
#pragma unroll
                for (int i = 0; i < 2; i++)
#pragma unroll
                    for (int j = 0; j < 3; j++)
                        wmma::store_matrix_sync(
                            &scratch[((wm & 1) * 32 + i * 16) * 96 + wn * 48 + j * 16],
                            cf[i][j], 96, wmma::mem_row_major);
            }
            __syncthreads();
#pragma unroll
            for (int itx = 0; itx < 2; itx++) {
                int task = tid + itx * 256;
                int r = task >> 3;
                int c4 = (task & 7) * 4;
                const int row = m0 + p * 64 + r;
                const int j = n0 + c4;
                const float* srow2 = &scratch[r * 96];
                float gr[4], gz[4], gn[4];
                *reinterpret_cast<float4*>(gr) = *reinterpret_cast<const float4*>(srow2 + c4);
                *reinterpret_cast<float4*>(gz) = *reinterpret_cast<const float4*>(srow2 + 32 + c4);
                *reinterpret_cast<float4*>(gn) = *reinterpret_cast<const float4*>(srow2 + 64 + c4);
                float br[4], bz[4], bn[4], xr[4], xz[4], xn[4], hh[4];
                *reinterpret_cast<float4*>(br) = *reinterpret_cast<const float4*>(bhh + j);
                *reinterpret_cast<float4*>(bz) = *reinterpret_cast<const float4*>(bhh + HDIM + j);
                *reinterpret_cast<float4*>(bn) = *reinterpret_cast<const float4*>(bhh + 2 * HDIM + j);
                const h16* gxp = gx + ((size_t)row * TWSTEPS + t) * GDIM;
                ld_h4(xr, gxp + j);
                ld_h4(xz, gxp + HDIM + j);
                ld_h4(xn, gxp + 2 * HDIM + j);
                ld_h4(hh, Hhi + (size_t)row * HDIM + j);
                h16 hb[4];
#pragma unroll
                for (int u = 0; u < 4; u++) {
                    float rr = sigmoid_f(xr[u] + gr[u] + br[u]);
                    float zz = sigmoid_f(xz[u] + gz[u] + bz[u]);
                    float nv = tanhf(xn[u] + rr * (gn[u] + bn[u]));
                    float h = (1.f - zz) * nv + zz * hh[u];
                    hb[u] = __float2half_rn(h);
                }
                *reinterpret_cast<ull*>(Hout + (size_t)row * HDIM + j) =
                    *reinterpret_cast<ull*>(hb);
            }
        }
        __syncthreads();
        grid.sync();
    }
}

// ---------------- t=0 GRU steps ----------------
__global__ void gru_init_h16(const h16* __restrict__ gx, const float* __restrict__ bhh,
                             h16* __restrict__ hi, int Mseq, int T)
{
    int i = blockIdx.x * blockDim.x + threadIdx.x;
    if (i >= Mseq * HDIM) return;
    int seq = i >> 8, j = i & 255;
    const h16* g = gx + (size_t)seq * T * GDIM;
    float xr = __half2float(g[j]);
    float xz = __half2float(g[j + HDIM]);
    float xn = __half2float(g[j + 2 * HDIM]);
    float r = sigmoid_f(xr + bhh[j]);
    float z = sigmoid_f(xz + bhh[j + HDIM]);
    float n = tanhf(xn + r * bhh[j + 2 * HDIM]);
    hi[i] = __float2half_rn((1.f - z) * n);
}

__global__ void gru_init_plain(const float* __restrict__ gx, const float* __restrict__ bhh,
                               float* __restrict__ hout, int Mseq, int T)
{
    int i = blockIdx.x * blockDim.x + threadIdx.x;
    if (i >= Mseq * HDIM) return;
    int seq = i >> 8, j = i & 255;
    const float* g = gx + (size_t)seq * T * GDIM;
    float r = sigmoid_f(g[j] + bhh[j]);
    float z = sigmoid_f(g[j + HDIM] + bhh[j + HDIM]);
    float n = tanhf(g[j + 2 * HDIM] + r * bhh[j + 2 * HDIM]);
    hout[i] = (1.f - z) * n;
}

// ---------------- fused multi-step GRU tail ----------------------------------
template <int NSEQ>
__global__ __launch_bounds__(256)
void gru_tail_fused(const float* __restrict__ h0, const h16* __restrict__ W16,
                    const float* __restrict__ bhh, const float* __restrict__ gx,
                    int T, float* __restrict__ hfinal)
{
    __shared__ float hs[HDIM][NSEQ];
    const int tid = threadIdx.x;
    const int seq0 = blockIdx.x * NSEQ;

    for (int i = tid; i < NSEQ * HDIM; i += 256) {
        int s = i / HDIM, k = i - s * HDIM;
        hs[k][s] = h0[(size_t)(seq0 + s) * HDIM + k];
    }
    __syncthreads();

    const int j = tid;
    const h16* wr = W16 + (size_t)j * HDIM;
    const h16* wz = W16 + (size_t)(HDIM + j) * HDIM;
    const h16* wn_ = W16 + (size_t)(2 * HDIM + j) * HDIM;
    const float br = bhh[j], bz = bhh[HDIM + j], bn = bhh[2 * HDIM + j];

    for (int t = 1; t < T; t++) {
        float ar[NSEQ], az[NSEQ], an[NSEQ];
#pragma unroll
        for (int s = 0; s < NSEQ; s++) { ar[s] = 0.f; az[s] = 0.f; an[s] = 0.f; }

#pragma unroll 4
        for (int k = 0; k < HDIM; k += 8) {
            uint4 vr = *reinterpret_cast<const uint4*>(wr + k);
            uint4 vz = *reinterpret_cast<const uint4*>(wz + k);
            uint4 vn = *reinterpret_cast<const uint4*>(wn_ + k);
            const h16* pr = reinterpret_cast<const h16*>(&vr);
            const h16* pz = reinterpret_cast<const h16*>(&vz);
            const h16* pn = reinterpret_cast<const h16*>(&vn);
#pragma unroll
            for (int u = 0; u < 8; u++) {
                float fr = __half2float(pr[u]);
                float fz = __half2float(pz[u]);
                float fn = __half2float(pn[u]);
#pragma unroll
                for (int s = 0; s < NSEQ; s++) {
                    float hv = hs[k + u][s];
                    ar[s] = fmaf(fr, hv, ar[s]);
                    az[s] = fmaf(fz, hv, az[s]);
                    an[s] = fmaf(fn, hv, an[s]);
                }
            }
        }
        __syncthreads();

        float hnew[NSEQ];
#pragma unroll
        for (int s = 0; s < NSEQ; s++) {
            const float* gxp = gx + ((size_t)(seq0 + s) * T + t) * GDIM;
            float r = sigmoid_f(gxp[j] + ar[s] + br);
            float z = sigmoid_f(gxp[HDIM + j] + az[s] + bz);
            float n = tanhf(gxp[2 * HDIM + j] + r * (an[s] + bn));
            hnew[s] = (1.f - z) * n + z * hs[j][s];
        }
#pragma unroll
        for (int s = 0; s < NSEQ; s++) hs[j][s] = hnew[s];
        __syncthreads();
    }

    for (int i = tid; i < NSEQ * HDIM; i += 256) {
        int s = i / HDIM, k = i - s * HDIM;
        hfinal[(size_t)(seq0 + s) * HDIM + k] = hs[k][s];
    }
}

// ---------------- fp32 SGEMM (review gx) ----------------
#define BM 128
#define BN 128
#define BK 8
__global__ __launch_bounds__(256, 2)
void sgemm_f32x2(const float* __restrict__ A, const float* __restrict__ W,
                 const float* __restrict__ bias, float* __restrict__ C,
                 int M, int K, int N)
{
    __shared__ float As[2][BK][BM];
    __shared__ float Bs[2][BK][BN];
    const int tid = threadIdx.x;
    const int m0 = blockIdx.y * BM;
    const int n0 = blockIdx.x * BN;
    const int a_m = tid & 127, a_kq = tid >> 7;
    const int b_n = tid >> 1,  b_kq = tid & 1;
    const bool a_valid = (m0 + a_m) < M;
    const float* Arow = A + (size_t)(a_valid ? (m0 + a_m) : 0) * K;
    const float* Brow = W + (size_t)(n0 + b_n) * K;
    const int tx = tid & 15, ty = tid >> 4;

    ull acc2[8][4];
#pragma unroll
    for (int i = 0; i < 8; i++)
#pragma unroll
        for (int j = 0; j < 4; j++) acc2[i][j] = 0ull;

    float4 av = make_float4(0.f, 0.f, 0.f, 0.f);
    if (a_valid) av = *reinterpret_cast<const float4*>(Arow + a_kq * 4);
    float4 bv = *reinterpret_cast<const float4*>(Brow + b_kq * 4);
    As[0][a_kq * 4 + 0][a_m] = av.x;  As[0][a_kq * 4 + 1][a_m] = av.y;
    As[0][a_kq * 4 + 2][a_m] = av.z;  As[0][a_kq * 4 + 3][a_m] = av.w;
    Bs[0][b_kq * 4 + 0][b_n] = bv.x;  Bs[0][b_kq * 4 + 1][b_n] = bv.y;
    Bs[0][b_kq * 4 + 2][b_n] = bv.z;  Bs[0][b_kq * 4 + 3][b_n] = bv.w;
    __syncthreads();

    int buf = 0;
    for (int kk = 0; kk < K; kk += BK) {
        const bool has_next = (kk + BK) < K;
        if (has_next) {
            if (a_valid) av = *reinterpret_cast<const float4*>(Arow + kk + BK + a_kq * 4);
            bv = *reinterpret_cast<const float4*>(Brow + kk + BK + b_kq * 4);
        }
#pragma unroll
        for (int k = 0; k < BK; k++) {
            float4 a0 = *reinterpret_cast<const float4*>(&As[buf][k][ty * 8]);
            float4 a1 = *reinterpret_cast<const float4*>(&As[buf][k][ty * 8 + 4]);
            ulonglong2 bq0 = *reinterpret_cast<const ulonglong2*>(&Bs[buf][k][tx * 8]);
            ulonglong2 bq1 = *reinterpret_cast<const ulonglong2*>(&Bs[buf][k][tx * 8 + 4]);
            ull bp[4] = {bq0.x, bq0.y, bq1.x, bq1.y};
            float a[8] = {a0.x, a0.y, a0.z, a0.w, a1.x, a1.y, a1.z, a1.w};
#pragma unroll
            for (int i = 0; i < 8; i++) {
                ull ad = dup2(a[i]);
#pragma unroll
                for (int j = 0; j < 4; j++) ffma2(acc2[i][j], ad, bp[j]);
            }
        }
        if (has_next) {
            int nb = buf ^ 1;
            As[nb][a_kq * 4 + 0][a_m] = av.x;  As[nb][a_kq * 4 + 1][a_m] = av.y;
            As[nb][a_kq * 4 + 2][a_m] = av.z;  As[nb][a_kq * 4 + 3][a_m] = av.w;
            Bs[nb][b_kq * 4 + 0][b_n] = bv.x;  Bs[nb][b_kq * 4 + 1][b_n] = bv.y;
            Bs[nb][b_kq * 4 + 2][b_n] = bv.z;  Bs[nb][b_kq * 4 + 3][b_n] = bv.w;
            __syncthreads();
            buf = nb;
        }
    }
#pragma unroll
    for (int i = 0; i < 8; i++) {
        int row = m0 + ty * 8 + i;
        if (row >= M) continue;
#pragma unroll
        for (int j = 0; j < 4; j++) {
            int col = n0 + tx * 8 + j * 2;
            float2 p = unpack2(acc2[i][j]);
            float2 bb = *reinterpret_cast<const float2*>(bias + col);
            float2 o; o.x = p.x + bb.x; o.y = p.y + bb.y;
            *reinterpret_cast<float2*>(C + (size_t)row * N + col) = o;
        }
    }
}

// ---------------- MLP ----------------
__global__ __launch_bounds__(128)
void mlp_kernel(const float* __restrict__ X,
                const float* __restrict__ W1, const float* __restrict__ b1,
                const float* __restrict__ W2, const float* __restrict__ b2,
                float* __restrict__ out)
{
    const int row = blockIdx.x;
    const int i = threadIdx.x;
    __shared__ float xs[HDIM];
    __shared__ float red[4];
    xs[i]       = X[(size_t)row * HDIM + i];
    xs[i + 128] = X[(size_t)row * HDIM + i + 128];
    __syncthreads();
    const float* w = W1 + (size_t)i * HDIM;
    float acc = b1[i];
#pragma unroll 8
    for (int k = 0; k < HDIM; k += 4) {
        float4 wv = *reinterpret_cast<const float4*>(w + k);
        acc = fmaf(wv.x, xs[k], acc);
        acc = fmaf(wv.y, xs[k + 1], acc);
        acc = fmaf(wv.z, xs[k + 2], acc);
        acc = fmaf(wv.w, xs[k + 3], acc);
    }
    const float scale = 1.0507009873554805f;
    const float alpha = 1.6732632423543772f;
    float s = scale * (acc > 0.f ? acc : alpha * (expf(acc) - 1.f));
    float v = s * W2[i];
#pragma unroll
    for (int off = 16; off > 0; off >>= 1)
        v += __shfl_down_sync(0xffffffffu, v, off);
    if ((i & 31) == 0) red[i >> 5] = v;
    __syncthreads();
    if (i == 0) out[row] = red[0] + red[1] + red[2] + red[3] + b2[0];
}

// ---------------- host orchestration ----------------
extern "C" void kernel_launch(void* const* d_in, const int* in_sizes, int n_in,
                              void* d_out, int out_size)
{
    (void)in_sizes; (void)n_in; (void)out_size;

    const int*   idx    = (const int*)  d_in[0];
    const float* emb    = (const float*)d_in[1];
    const float* w_Wih  = (const float*)d_in[2];
    const float* w_Whh  = (const float*)d_in[3];
    const float* w_bih  = (const float*)d_in[4];
    const float* w_bhh  = (const float*)d_in[5];
    const float* s_Wih  = (const float*)d_in[6];
    const float* s_Whh  = (const float*)d_in[7];
    const float* s_bih  = (const float*)d_in[8];
    const float* s_bhh  = (const float*)d_in[9];
    const float* r_Wih  = (const float*)d_in[10];
    const float* r_Whh  = (const float*)d_in[11];
    const float* r_bih  = (const float*)d_in[12];
    const float* r_bhh  = (const float*)d_in[13];
    const float* rfc_W1 = (const float*)d_in[14];
    const float* rfc_b1 = (const float*)d_in[15];
    const float* rfc_W2 = (const float*)d_in[16];
    const float* rfc_b2 = (const float*)d_in[17];
    const float* pfc_W1 = (const float*)d_in[18];
    const float* pfc_b1 = (const float*)d_in[19];
    const float* pfc_W2 = (const float*)d_in[20];
    const float* pfc_b2 = (const float*)d_in[21];
    float* out = (float*)d_out;

    float *GXs, *GXr, *HsA, *HsB, *HrA, *HrB;
    h16 *GXw, *Xh, *WihH, *WhhH, *WsH, *WshhH, *WrhhH, *SHiA, *SHiB;
    cudaGetSymbolAddress((void**)&GXw, g_GXw);
    cudaGetSymbolAddress((void**)&GXs, g_GXs);
    cudaGetSymbolAddress((void**)&GXr, g_GXr);
    cudaGetSymbolAddress((void**)&HsA, g_HsA);
    cudaGetSymbolAddress((void**)&HsB, g_HsB);
    cudaGetSymbolAddress((void**)&HrA, g_HrA);
    cudaGetSymbolAddress((void**)&HrB, g_HrB);
    cudaGetSymbolAddress((void**)&Xh, g_Xh);
    cudaGetSymbolAddress((void**)&WihH, g_WihH);
    cudaGetSymbolAddress((void**)&WhhH, g_WhhH);
    cudaGetSymbolAddress((void**)&WsH, g_WsH);
    cudaGetSymbolAddress((void**)&WshhH, g_WshhH);
    cudaGetSymbolAddress((void**)&WrhhH, g_WrhhH);
    cudaGetSymbolAddress((void**)&SHiA, g_SHiA);
    cudaGetSymbolAddress((void**)&SHiB, g_SHiB);

    const int SMEM_GEMM = 65536;   // max(3*GEMM_BUF=61440, scratch 65536)
    cudaFuncSetAttribute(gemm_wmma2<h16>, cudaFuncAttributeMaxDynamicSharedMemorySize, SMEM_GEMM);
    cudaFuncSetAttribute(gemm_wmma2<float>, cudaFuncAttributeMaxDynamicSharedMemorySize, SMEM_GEMM);
    cudaFuncSetAttribute(gru_word_persistent, cudaFuncAttributeMaxDynamicSharedMemorySize, PSMEM);

    // ---- prep ----
    split_w_single<<<(GDIM * KPAD + 255) / 256, 256>>>(w_Wih, WihH, GDIM, EDIM, KPAD);
    {
        int n4 = GDIM * HDIM / 4;
        split_w_quad<<<(4 * n4 + 255) / 256, 256>>>(w_Whh, WhhH, s_Wih, WsH,
                                                    s_Whh, WshhH, r_Whh, WrhhH, n4);
    }
    gather_h16_kernel<<<(int)(((size_t)MW * KP4 + 255) / 256), 256>>>(idx, emb, Xh);

    // ---- word level: gx (fp16 out) ----
    gemm_wmma2<h16><<<dim3(GDIM / 128, MW / 128), 256, SMEM_GEMM>>>(Xh, WihH,
                                                                    w_bih, GXw, KPAD, GDIM);

    // t=0, then persistent cooperative loop t=1..31 (fp16 h, W smem-resident)
    gru_init_h16<<<(NW * HDIM + 255) / 256, 256>>>(GXw, w_bhh, SHiA, NW, TWSTEPS);
    {
        cudaLaunchConfig_t cfg = {};
        cfg.gridDim = dim3(HDIM / 32, NW / 128);    // (8, 32) = 256 CTAs
        cfg.blockDim = dim3(256, 1, 1);
        cfg.dynamicSmemBytes = PSMEM;
        cudaLaunchAttribute attr;
        attr.id = cudaLaunchAttributeCooperative;
        attr.val.cooperative = 1;
        cfg.attrs = &attr;
        cfg.numAttrs = 1;
        cudaLaunchKernelEx(&cfg, gru_word_persistent,
                           SHiA, SHiB, (const h16*)WhhH,
                           (const float*)w_bhh, (const h16*)GXw);
    }
    h16* sent_hi = SHiB;   // 31 iterations -> B buffers

    // ---- sentence level ----
    gemm_wmma2<float><<<dim3(GDIM / 128, (NS * TSSTEPS) / 128), 256, SMEM_GEMM>>>(
        sent_hi, WsH, s_bih, GXs, HDIM, GDIM);

    gru_init_plain<<<(NS * HDIM + 255) / 256, 256>>>(GXs, s_bhh, HsA, NS, TSSTEPS);
    gru_tail_fused<4><<<NS / 4, 256>>>(HsA, WshhH, s_bhh, GXs, TSSTEPS, HsB);
    const float* p_batch = HsB;

    // r_stars -> out[16 .. 272)
    mlp_kernel<<<NS, 128>>>(p_batch, rfc_W1, rfc_b1, rfc_W2, rfc_b2, out + NR);

    // ---- review level ----
    {
        dim3 grid(GDIM / BN, (NR * TRSTEPS + BM - 1) / BM);
        sgemm_f32x2<<<grid, 256>>>(p_batch, r_Wih, r_bih, GXr, NR * TRSTEPS, HDIM, GDIM);
    }
    gru_init_plain<<<(NR * HDIM + 255) / 256, 256>>>(GXr, r_bhh, HrA, NR, TRSTEPS);
    gru_tail_fused<1><<<NR, 256>>>(HrA, WrhhH, r_bhh, GXr, TRSTEPS, HrB);

    // b_stars -> out[0 .. 16)
    mlp_kernel<<<NR, 128>>>(HrB, pfc_W1, pfc_b1, pfc_W2, pfc_b2, out);
}

// round 16
// speedup vs baseline: 1.3055x; 1.0085x over previous
#include <cuda_runtime.h>
#include <cuda_fp16.h>
#include <mma.h>
#include <cooperative_groups.h>
#include <math.h>
#include <stdint.h>

using namespace nvcuda;

// ---------------- problem dims ----------------
#define HDIM 256
#define GDIM 768
#define EDIM 200
#define NW 4096
#define TWSTEPS 32
#define NS 256
#define TSSTEPS 16
#define NR 16
#define TRSTEPS 16
#define MW (NW * TWSTEPS)
#define KPAD 224
#define KP4 (KPAD / 4)

typedef unsigned long long ull;
typedef __half h16;

// ---------------- scratch ----------------
__device__ __align__(16) h16 g_GXw[(size_t)MW * GDIM];   // fp16 word input gates
__device__ float g_GXs[(size_t)NS * TSSTEPS * GDIM];
__device__ float g_GXr[(size_t)NR * TRSTEPS * GDIM];
__device__ float g_HsA[NS * HDIM], g_HsB[NS * HDIM];
__device__ float g_HrA[NR * HDIM], g_HrB[NR * HDIM];
__device__ __align__(16) h16 g_Xh[(size_t)MW * KPAD];
__device__ __align__(16) h16 g_WihH[GDIM * KPAD];
__device__ __align__(16) h16 g_WhhH[GDIM * HDIM];
__device__ __align__(16) h16 g_WsH [GDIM * HDIM];
__device__ __align__(16) h16 g_WshhH[GDIM * HDIM];
__device__ __align__(16) h16 g_WrhhH[GDIM * HDIM];
__device__ __align__(16) h16 g_SHiA[NW * HDIM], g_SHiB[NW * HDIM];
__device__ unsigned int g_bar[32];     // per-m0-group arrival counters

// ---------------- helpers ----------------
__device__ __forceinline__ float sigmoid_f(float x) { return 1.f / (1.f + expf(-x)); }
__device__ __forceinline__ ull pack2(float lo, float hi) {
    ull r; asm("mov.b64 %0, {%1, %2};" : "=l"(r) : "f"(lo), "f"(hi)); return r;
}
__device__ __forceinline__ ull dup2(float v) { return pack2(v, v); }
__device__ __forceinline__ void ffma2(ull& d, ull a, ull b) {
    asm("fma.rn.f32x2 %0, %1, %2, %3;" : "=l"(d) : "l"(a), "l"(b), "l"(d));
}
__device__ __forceinline__ float2 unpack2(ull v) {
    float2 f; asm("mov.b64 {%0, %1}, %2;" : "=f"(f.x), "=f"(f.y) : "l"(v)); return f;
}
__device__ __forceinline__ void cp16(uint32_t s, const void* g) {
    asm volatile("cp.async.cg.shared.global [%0], [%1], 16;" :: "r"(s), "l"(g));
}
#define CP_COMMIT() asm volatile("cp.async.commit_group;" ::: "memory")
#define CP_WAIT(n)  asm volatile("cp.async.wait_group %0;" :: "n"(n) : "memory")

__device__ __forceinline__ void ld_h4(float* o, const h16* p) {
    ull v = *reinterpret_cast<const ull*>(p);
    const h16* q = reinterpret_cast<const h16*>(&v);
    o[0] = __half2float(q[0]); o[1] = __half2float(q[1]);
    o[2] = __half2float(q[2]); o[3] = __half2float(q[3]);
}
// L2-coherent variant (bypasses possibly-stale L1) for cross-CTA h reads
__device__ __forceinline__ void ld_h4_cg(float* o, const h16* p) {
    ull v = __ldcg(reinterpret_cast<const ull*>(p));
    const h16* q = reinterpret_cast<const h16*>(&v);
    o[0] = __half2float(q[0]); o[1] = __half2float(q[1]);
    o[2] = __half2float(q[2]); o[3] = __half2float(q[3]);
}

// ---------------- prep kernels ----------------
__global__ void split_w_single(const float* __restrict__ src, h16* __restrict__ dst,
                               int rows, int cs, int cd)
{
    int i = blockIdx.x * blockDim.x + threadIdx.x;
    if (i >= rows * cd) return;
    int r = i / cd, c = i - r * cd;
    float v = (c < cs) ? src[(size_t)r * cs + c] : 0.f;
    dst[i] = __float2half_rn(v);
}

__global__ void split_w_quad(const float* s0, h16* d0, const float* s1, h16* d1,
                             const float* s2, h16* d2, const float* s3, h16* d3,
                             int n4)
{
    int i = blockIdx.x * blockDim.x + threadIdx.x;
    int mat = i / n4;
    int off = (i - mat * n4) * 4;
    if (mat >= 4) return;
    const float* s = (mat == 0) ? s0 : (mat == 1) ? s1 : (mat == 2) ? s2 : s3;
    h16* d = (mat == 0) ? d0 : (mat == 1) ? d1 : (mat == 2) ? d2 : d3;
    float4 v = *reinterpret_cast<const float4*>(s + off);
    h16 hb[4];
    hb[0] = __float2half_rn(v.x); hb[1] = __float2half_rn(v.y);
    hb[2] = __float2half_rn(v.z); hb[3] = __float2half_rn(v.w);
    *reinterpret_cast<ull*>(d + off) = *reinterpret_cast<ull*>(hb);
}

__global__ void gather_h16_kernel(const int* __restrict__ idx, const float* __restrict__ emb,
                                  h16* __restrict__ hi)
{
    size_t id = (size_t)blockIdx.x * blockDim.x + threadIdx.x;
    if (id >= (size_t)MW * KP4) return;
    int row = (int)(id / KP4);
    int c4 = (int)(id - (size_t)row * KP4) * 4;
    float4 v = make_float4(0.f, 0.f, 0.f, 0.f);
    if (c4 < EDIM)
        v = *reinterpret_cast<const float4*>(emb + (size_t)idx[row] * EDIM + c4);
    h16 hb[4];
    hb[0] = __float2half_rn(v.x); hb[1] = __float2half_rn(v.y);
    hb[2] = __float2half_rn(v.z); hb[3] = __float2half_rn(v.w);
    *reinterpret_cast<ull*>(hi + (size_t)row * KPAD + c4) = *reinterpret_cast<ull*>(hb);
}

// ---------------- wmma fp16 GEMM: C = A@W^T + bias (3-stage pipeline) -------
#define LDT2 40
#define TBY (128 * LDT2 * 2)         // 10240B per matrix tile
#define GEMM_BUF (2 * TBY)           // per stage: A + B

template <typename OutT>
__global__ __launch_bounds__(256, 2)
void gemm_wmma2(const h16* __restrict__ Ahp, const h16* __restrict__ Whp,
                const float* __restrict__ bias, OutT* __restrict__ C,
                int K, int N)
{
    extern __shared__ __align__(128) char sm[];
    const uint32_t sbase = (uint32_t)__cvta_generic_to_shared(sm);
    float* scratch = reinterpret_cast<float*>(sm);

    const int tid = threadIdx.x;
    const int wid = tid >> 5;
    const int m0 = blockIdx.y * 128, n0 = blockIdx.x * 128;
    const int wm = wid & 3, wn = wid >> 2;

    const int lr = tid >> 1;
    const int lq = (tid & 1) * 16;

    const h16* gA = Ahp + (size_t)(m0 + lr) * K + lq;
    const h16* gB = Whp + (size_t)(n0 + lr) * K + lq;
    const uint32_t srow = lr * LDT2 * 2 + lq * 2;

    const int ntile = K / 32;

    wmma::fragment<wmma::accumulator, 16, 16, 16, float> cf[2][4];
#pragma unroll
    for (int i = 0; i < 2; i++)
#pragma unroll
        for (int j = 0; j < 4; j++) wmma::fill_fragment(cf[i][j], 0.0f);

    auto issue = [&](int it, int stg) {
        const int kk = it * 32;
        uint32_t base = sbase + stg * GEMM_BUF;
        cp16(base + srow,            gA + kk);
        cp16(base + srow + 16,       gA + kk + 8);
        cp16(base + TBY + srow,      gB + kk);
        cp16(base + TBY + srow + 16, gB + kk + 8);
    };

    issue(0, 0); CP_COMMIT();
    if (ntile > 1) { issue(1, 1); CP_COMMIT(); }

    for (int it = 0; it < ntile; it++) {
        if (it + 1 < ntile) { CP_WAIT(1); } else { CP_WAIT(0); }
        __syncthreads();
        if (it + 2 < ntile) { issue(it + 2, (it + 2) % 3); CP_COMMIT(); }

        const h16* tA = reinterpret_cast<const h16*>(sm + (it % 3) * GEMM_BUF);
        const h16* tB = tA + 128 * LDT2;

#pragma unroll
        for (int ks = 0; ks < 32; ks += 16) {
            wmma::fragment<wmma::matrix_a, 16, 16, 16, h16, wmma::row_major> ah[2];
            wmma::fragment<wmma::matrix_b, 16, 16, 16, h16, wmma::col_major> bh[4];
#pragma unroll
            for (int i = 0; i < 2; i++)
                wmma::load_matrix_sync(ah[i], tA + (wm * 32 + i * 16) * LDT2 + ks, LDT2);
#pragma unroll
            for (int j = 0; j < 4; j++)
                wmma::load_matrix_sync(bh[j], tB + (wn * 64 + j * 16) * LDT2 + ks, LDT2);
#pragma unroll
            for (int i = 0; i < 2; i++)
#pragma unroll
                for (int j = 0; j < 4; j++)
                    wmma::mma_sync(cf[i][j], ah[i], bh[j], cf[i][j]);
        }
    }
    __syncthreads();

#pragma unroll
    for (int i = 0; i < 2; i++)
#pragma unroll
        for (int j = 0; j < 4; j++)
            wmma::store_matrix_sync(&scratch[(wm * 32 + i * 16) * 128 + wn * 64 + j * 16],
                                    cf[i][j], 128, wmma::mem_row_major);
    __syncthreads();

#pragma unroll
    for (int itx = 0; itx < 16; itx++) {
        int idx4 = tid + itx * 256;
        int r = idx4 >> 5;
        int c4 = (idx4 & 31) * 4;
        float4 v = *reinterpret_cast<const float4*>(&scratch[r * 128 + c4]);
        float4 b = *reinterpret_cast<const float4*>(&bias[n0 + c4]);
        v.x += b.x; v.y += b.y; v.z += b.z; v.w += b.w;
        if constexpr (sizeof(OutT) == 4) {
            *reinterpret_cast<float4*>(&C[(size_t)(m0 + r) * N + n0 + c4]) = v;
        } else {
            h16 hb[4];
            hb[0] = __float2half_rn(v.x); hb[1] = __float2half_rn(v.y);
            hb[2] = __float2half_rn(v.z); hb[3] = __float2half_rn(v.w);
            *reinterpret_cast<ull*>(&C[(size_t)(m0 + r) * N + n0 + c4]) =
                *reinterpret_cast<ull*>(hb);
        }
    }
}

// ---------------- persistent word-recurrent loop, group-local barriers -------
// CTA = 128 rows x 32 h-cols. W smem-resident. grid (8, 32), occ 2.
// Step boundary: 8-CTA arrival counter per m0 group (NOT grid.sync).
#define WROWS 96
#define WLD 264
#define WBYTES (WROWS * WLD * 2)       // 50688
#define ABUF (128 * LDT2 * 2)          // 10240 per A buffer
#define PSMEM (WBYTES + 3 * ABUF)      // 81408

__global__ __launch_bounds__(256, 2)
void gru_word_persistent(h16* __restrict__ sA, h16* __restrict__ sB,
                         const h16* __restrict__ Whp,
                         const float* __restrict__ bhh, const h16* __restrict__ gx,
                         unsigned int* __restrict__ bar)
{
    extern __shared__ __align__(128) char sm[];
    const uint32_t sbase = (uint32_t)__cvta_generic_to_shared(sm);
    const h16* Wsm = reinterpret_cast<const h16*>(sm);
    float* scratch = reinterpret_cast<float*>(sm + WBYTES);   // 64x96 fp32 (24KB)

    const int tid = threadIdx.x;
    const int wid = tid >> 5;
    const int n0 = blockIdx.x * 32;
    const int m0 = blockIdx.y * 128;
    const int grp = blockIdx.y;
    const int wm = wid & 3;
    const int wn = wid >> 2;

    // ---- prologue: load W tile once ----
    for (int task = tid; task < WROWS * 32; task += 256) {
        int rt = task >> 5;
        int q = task & 31;
        int gate = rt >> 5, col = rt & 31;
        size_t srcoff = (size_t)(gate * HDIM + n0 + col) * HDIM + q * 8;
        cp16(sbase + rt * (WLD * 2) + q * 16, Whp + srcoff);
    }
    CP_COMMIT(); CP_WAIT(0);
    __syncthreads();

    const int lr = tid >> 1;
    const int lq = (tid & 1) * 16;
    const uint32_t arow = lr * (LDT2 * 2) + lq * 2;

    for (int t = 1; t < TWSTEPS; t++) {
        const int cur = (t - 1) & 1;
        const h16* Hhi  = cur ? sB : sA;
        h16*       Hout = cur ? sA : sB;

        const h16* gAh = Hhi + (size_t)(m0 + lr) * HDIM + lq;

        auto issue = [&](int it, int stg) {
            const int kk = it * 32;
            uint32_t base = sbase + WBYTES + stg * ABUF;
            cp16(base + arow,      gAh + kk);
            cp16(base + arow + 16, gAh + kk + 8);
        };

        wmma::fragment<wmma::accumulator, 16, 16, 16, float> cf[2][3];
#pragma unroll
        for (int i = 0; i < 2; i++)
#pragma unroll
            for (int j = 0; j < 3; j++) wmma::fill_fragment(cf[i][j], 0.0f);

        issue(0, 0); CP_COMMIT();
        issue(1, 1); CP_COMMIT();

        const int ntile = HDIM / 32;
        for (int it = 0; it < ntile; it++) {
            if (it + 1 < ntile) { CP_WAIT(1); } else { CP_WAIT(0); }
            __syncthreads();
            if (it + 2 < ntile) { issue(it + 2, (it + 2) % 3); CP_COMMIT(); }

            const h16* tA = reinterpret_cast<const h16*>(sm + WBYTES + (it % 3) * ABUF);
            const int kk = it * 32;

#pragma unroll
            for (int ks = 0; ks < 32; ks += 16) {
                wmma::fragment<wmma::matrix_a, 16, 16, 16, h16, wmma::row_major> ah0, ah1;
                wmma::load_matrix_sync(ah0, tA + (wm * 32) * LDT2 + ks, LDT2);
                wmma::load_matrix_sync(ah1, tA + (wm * 32 + 16) * LDT2 + ks, LDT2);
#pragma unroll
                for (int j = 0; j < 3; j++) {
                    wmma::fragment<wmma::matrix_b, 16, 16, 16, h16, wmma::col_major> bh;
                    wmma::load_matrix_sync(bh, Wsm + (wn * 48 + j * 16) * WLD + kk + ks, WLD);
                    wmma::mma_sync(cf[0][j], ah0, bh, cf[0][j]);
                    wmma::mma_sync(cf[1][j], ah1, bh, cf[1][j]);
                }
            }
        }
        __syncthreads();

        // ---- epilogue in 2 row-passes ----
#pragma unroll
        for (int p = 0; p < 2; p++) {
            __syncthreads();
            if ((wm >> 1) == p) {
#pragma unroll
                for (int i = 0; i < 2; i++)
#pragma unroll
                    for (int j = 0; j < 3; j++)
                        wmma::store_matrix_sync(
                            &scratch[((wm & 1) * 32 + i * 16) * 96 + wn * 48 + j * 16],
                            cf[i][j], 96, wmma::mem_row_major);
            }
            __syncthreads();
#pragma unroll
            for (int itx = 0; itx < 2; itx++) {
                int task = tid + itx * 256;
                int r = task >> 3;
                int c4 = (task & 7) * 4;
                const int row = m0 + p * 64 + r;
                const int j = n0 + c4;
                const float* srow2 = &scratch[r * 96];
                float gr[4], gz[4], gn[4];
                *reinterpret_cast<float4*>(gr) = *reinterpret_cast<const float4*>(srow2 + c4);
                *reinterpret_cast<float4*>(gz) = *reinterpret_cast<const float4*>(srow2 + 32 + c4);
                *reinterpret_cast<float4*>(gn) = *reinterpret_cast<const float4*>(srow2 + 64 + c4);
                float br[4], bz[4], bn[4], xr[4], xz[4], xn[4], hh[4];
                *reinterpret_cast<float4*>(br) = *reinterpret_cast<const float4*>(bhh + j);
                *reinterpret_cast<float4*>(bz) = *reinterpret_cast<const float4*>(bhh + HDIM + j);
                *reinterpret_cast<float4*>(bn) = *reinterpret_cast<const float4*>(bhh + 2 * HDIM + j);
                const h16* gxp = gx + ((size_t)row * TWSTEPS + t) * GDIM;
                ld_h4(xr, gxp + j);
                ld_h4(xz, gxp + HDIM + j);
                ld_h4(xn, gxp + 2 * HDIM + j);
                ld_h4_cg(hh, Hhi + (size_t)row * HDIM + j);
                h16 hb[4];
#pragma unroll
                for (int u = 0; u < 4; u++) {
                    float rr = sigmoid_f(xr[u] + gr[u] + br[u]);
                    float zz = sigmoid_f(xz[u] + gz[u] + bz[u]);
                    float nv = tanhf(xn[u] + rr * (gn[u] + bn[u]));
                    float h = (1.f - zz) * nv + zz * hh[u];
                    hb[u] = __float2half_rn(h);
                }
                *reinterpret_cast<ull*>(Hout + (size_t)row * HDIM + j) =
                    *reinterpret_cast<ull*>(hb);
            }
        }
        __syncthreads();

        // ---- group-local step barrier (8 CTAs sharing m0) ----
        if (t + 1 < TWSTEPS) {
            if (tid == 0) {
                __threadfence();                       // h writes -> L2 before arrival
                atomicAdd(&bar[grp], 1u);
                const unsigned int target = 8u * (unsigned int)t;
                while (atomicAdd(&bar[grp], 0u) < target) {}
            }
            __syncthreads();
        }
    }
}

// ---------------- t=0 GRU steps ----------------
__global__ void gru_init_h16(const h16* __restrict__ gx, const float* __restrict__ bhh,
                             h16* __restrict__ hi, int Mseq, int T)
{
    int i = blockIdx.x * blockDim.x + threadIdx.x;
    if (i >= Mseq * HDIM) return;
    int seq = i >> 8, j = i & 255;
    const h16* g = gx + (size_t)seq * T * GDIM;
    float xr = __half2float(g[j]);
    float xz = __half2float(g[j + HDIM]);
    float xn = __half2float(g[j + 2 * HDIM]);
    float r = sigmoid_f(xr + bhh[j]);
    float z = sigmoid_f(xz + bhh[j + HDIM]);
    float n = tanhf(xn + r * bhh[j + 2 * HDIM]);
    hi[i] = __float2half_rn((1.f - z) * n);
}

__global__ void gru_init_plain(const float* __restrict__ gx, const float* __restrict__ bhh,
                               float* __restrict__ hout, int Mseq, int T)
{
    int i = blockIdx.x * blockDim.x + threadIdx.x;
    if (i >= Mseq * HDIM) return;
    int seq = i >> 8, j = i & 255;
    const float* g = gx + (size_t)seq * T * GDIM;
    float r = sigmoid_f(g[j] + bhh[j]);
    float z = sigmoid_f(g[j + HDIM] + bhh[j + HDIM]);
    float n = tanhf(g[j + 2 * HDIM] + r * bhh[j + 2 * HDIM]);
    hout[i] = (1.f - z) * n;
}

// ---------------- fused multi-step GRU tail ----------------------------------
template <int NSEQ>
__global__ __launch_bounds__(256)
void gru_tail_fused(const float* __restrict__ h0, const h16* __restrict__ W16,
                    const float* __restrict__ bhh, const float* __restrict__ gx,
                    int T, float* __restrict__ hfinal)
{
    __shared__ float hs[HDIM][NSEQ];
    const int tid = threadIdx.x;
    const int seq0 = blockIdx.x * NSEQ;

    for (int i = tid; i < NSEQ * HDIM; i += 256) {
        int s = i / HDIM, k = i - s * HDIM;
        hs[k][s] = h0[(size_t)(seq0 + s) * HDIM + k];
    }
    __syncthreads();

    const int j = tid;
    const h16* wr = W16 + (size_t)j * HDIM;
    const h16* wz = W16 + (size_t)(HDIM + j) * HDIM;
    const h16* wn_ = W16 + (size_t)(2 * HDIM + j) * HDIM;
    const float br = bhh[j], bz = bhh[HDIM + j], bn = bhh[2 * HDIM + j];

    for (int t = 1; t < T; t++) {
        float ar[NSEQ], az[NSEQ], an[NSEQ];
#pragma unroll
        for (int s = 0; s < NSEQ; s++) { ar[s] = 0.f; az[s] = 0.f; an[s] = 0.f; }

#pragma unroll 4
        for (int k = 0; k < HDIM; k += 8) {
            uint4 vr = *reinterpret_cast<const uint4*>(wr + k);
            uint4 vz = *reinterpret_cast<const uint4*>(wz + k);
            uint4 vn = *reinterpret_cast<const uint4*>(wn_ + k);
            const h16* pr = reinterpret_cast<const h16*>(&vr);
            const h16* pz = reinterpret_cast<const h16*>(&vz);
            const h16* pn = reinterpret_cast<const h16*>(&vn);
#pragma unroll
            for (int u = 0; u < 8; u++) {
                float fr = __half2float(pr[u]);
                float fz = __half2float(pz[u]);
                float fn = __half2float(pn[u]);
#pragma unroll
                for (int s = 0; s < NSEQ; s++) {
                    float hv = hs[k + u][s];
                    ar[s] = fmaf(fr, hv, ar[s]);
                    az[s] = fmaf(fz, hv, az[s]);
                    an[s] = fmaf(fn, hv, an[s]);
                }
            }
        }
        __syncthreads();

        float hnew[NSEQ];
#pragma unroll
        for (int s = 0; s < NSEQ; s++) {
            const float* gxp = gx + ((size_t)(seq0 + s) * T + t) * GDIM;
            float r = sigmoid_f(gxp[j] + ar[s] + br);
            float z = sigmoid_f(gxp[HDIM + j] + az[s] + bz);
            float n = tanhf(gxp[2 * HDIM + j] + r * (an[s] + bn));
            hnew[s] = (1.f - z) * n + z * hs[j][s];
        }
#pragma unroll
        for (int s = 0; s < NSEQ; s++) hs[j][s] = hnew[s];
        __syncthreads();
    }

    for (int i = tid; i < NSEQ * HDIM; i += 256) {
        int s = i / HDIM, k = i - s * HDIM;
        hfinal[(size_t)(seq0 + s) * HDIM + k] = hs[k][s];
    }
}

// ---------------- fp32 SGEMM (review gx) ----------------
#define BM 128
#define BN 128
#define BK 8
__global__ __launch_bounds__(256, 2)
void sgemm_f32x2(const float* __restrict__ A, const float* __restrict__ W,
                 const float* __restrict__ bias, float* __restrict__ C,
                 int M, int K, int N)
{
    __shared__ float As[2][BK][BM];
    __shared__ float Bs[2][BK][BN];
    const int tid = threadIdx.x;
    const int m0 = blockIdx.y * BM;
    const int n0 = blockIdx.x * BN;
    const int a_m = tid & 127, a_kq = tid >> 7;
    const int b_n = tid >> 1,  b_kq = tid & 1;
    const bool a_valid = (m0 + a_m) < M;
    const float* Arow = A + (size_t)(a_valid ? (m0 + a_m) : 0) * K;
    const float* Brow = W + (size_t)(n0 + b_n) * K;
    const int tx = tid & 15, ty = tid >> 4;

    ull acc2[8][4];
#pragma unroll
    for (int i = 0; i < 8; i++)
#pragma unroll
        for (int j = 0; j < 4; j++) acc2[i][j] = 0ull;

    float4 av = make_float4(0.f, 0.f, 0.f, 0.f);
    if (a_valid) av = *reinterpret_cast<const float4*>(Arow + a_kq * 4);
    float4 bv = *reinterpret_cast<const float4*>(Brow + b_kq * 4);
    As[0][a_kq * 4 + 0][a_m] = av.x;  As[0][a_kq * 4 + 1][a_m] = av.y;
    As[0][a_kq * 4 + 2][a_m] = av.z;  As[0][a_kq * 4 + 3][a_m] = av.w;
    Bs[0][b_kq * 4 + 0][b_n] = bv.x;  Bs[0][b_kq * 4 + 1][b_n] = bv.y;
    Bs[0][b_kq * 4 + 2][b_n] = bv.z;  Bs[0][b_kq * 4 + 3][b_n] = bv.w;
    __syncthreads();

    int buf = 0;
    for (int kk = 0; kk < K; kk += BK) {
        const bool has_next = (kk + BK) < K;
        if (has_next) {
            if (a_valid) av = *reinterpret_cast<const float4*>(Arow + kk + BK + a_kq * 4);
            bv = *reinterpret_cast<const float4*>(Brow + kk + BK + b_kq * 4);
        }
#pragma unroll
        for (int k = 0; k < BK; k++) {
            float4 a0 = *reinterpret_cast<const float4*>(&As[buf][k][ty * 8]);
            float4 a1 = *reinterpret_cast<const float4*>(&As[buf][k][ty * 8 + 4]);
            ulonglong2 bq0 = *reinterpret_cast<const ulonglong2*>(&Bs[buf][k][tx * 8]);
            ulonglong2 bq1 = *reinterpret_cast<const ulonglong2*>(&Bs[buf][k][tx * 8 + 4]);
            ull bp[4] = {bq0.x, bq0.y, bq1.x, bq1.y};
            float a[8] = {a0.x, a0.y, a0.z, a0.w, a1.x, a1.y, a1.z, a1.w};
#pragma unroll
            for (int i = 0; i < 8; i++) {
                ull ad = dup2(a[i]);
#pragma unroll
                for (int j = 0; j < 4; j++) ffma2(acc2[i][j], ad, bp[j]);
            }
        }
        if (has_next) {
            int nb = buf ^ 1;
            As[nb][a_kq * 4 + 0][a_m] = av.x;  As[nb][a_kq * 4 + 1][a_m] = av.y;
            As[nb][a_kq * 4 + 2][a_m] = av.z;  As[nb][a_kq * 4 + 3][a_m] = av.w;
            Bs[nb][b_kq * 4 + 0][b_n] = bv.x;  Bs[nb][b_kq * 4 + 1][b_n] = bv.y;
            Bs[nb][b_kq * 4 + 2][b_n] = bv.z;  Bs[nb][b_kq * 4 + 3][b_n] = bv.w;
            __syncthreads();
            buf = nb;
        }
    }
#pragma unroll
    for (int i = 0; i < 8; i++) {
        int row = m0 + ty * 8 + i;
        if (row >= M) continue;
#pragma unroll
        for (int j = 0; j < 4; j++) {
            int col = n0 + tx * 8 + j * 2;
            float2 p = unpack2(acc2[i][j]);
            float2 bb = *reinterpret_cast<const float2*>(bias + col);
            float2 o; o.x = p.x + bb.x; o.y = p.y + bb.y;
            *reinterpret_cast<float2*>(C + (size_t)row * N + col) = o;
        }
    }
}

// ---------------- MLP ----------------
__global__ __launch_bounds__(128)
void mlp_kernel(const float* __restrict__ X,
                const float* __restrict__ W1, const float* __restrict__ b1,
                const float* __restrict__ W2, const float* __restrict__ b2,
                float* __restrict__ out)
{
    const int row = blockIdx.x;
    const int i = threadIdx.x;
    __shared__ float xs[HDIM];
    __shared__ float red[4];
    xs[i]       = X[(size_t)row * HDIM + i];
    xs[i + 128] = X[(size_t)row * HDIM + i + 128];
    __syncthreads();
    const float* w = W1 + (size_t)i * HDIM;
    float acc = b1[i];
#pragma unroll 8
    for (int k = 0; k < HDIM; k += 4) {
        float4 wv = *reinterpret_cast<const float4*>(w + k);
        acc = fmaf(wv.x, xs[k], acc);
        acc = fmaf(wv.y, xs[k + 1], acc);
        acc = fmaf(wv.z, xs[k + 2], acc);
        acc = fmaf(wv.w, xs[k + 3], acc);
    }
    const float scale = 1.0507009873554805f;
    const float alpha = 1.6732632423543772f;
    float s = scale * (acc > 0.f ? acc : alpha * (expf(acc) - 1.f));
    float v = s * W2[i];
#pragma unroll
    for (int off = 16; off > 0; off >>= 1)
        v += __shfl_down_sync(0xffffffffu, v, off);
    if ((i & 31) == 0) red[i >> 5] = v;
    __syncthreads();
    if (i == 0) out[row] = red[0] + red[1] + red[2] + red[3] + b2[0];
}

// ---------------- host orchestration ----------------
extern "C" void kernel_launch(void* const* d_in, const int* in_sizes, int n_in,
                              void* d_out, int out_size)
{
    (void)in_sizes; (void)n_in; (void)out_size;

    const int*   idx    = (const int*)  d_in[0];
    const float* emb    = (const float*)d_in[1];
    const float* w_Wih  = (const float*)d_in[2];
    const float* w_Whh  = (const float*)d_in[3];
    const float* w_bih  = (const float*)d_in[4];
    const float* w_bhh  = (const float*)d_in[5];
    const float* s_Wih  = (const float*)d_in[6];
    const float* s_Whh  = (const float*)d_in[7];
    const float* s_bih  = (const float*)d_in[8];
    const float* s_bhh  = (const float*)d_in[9];
    const float* r_Wih  = (const float*)d_in[10];
    const float* r_Whh  = (const float*)d_in[11];
    const float* r_bih  = (const float*)d_in[12];
    const float* r_bhh  = (const float*)d_in[13];
    const float* rfc_W1 = (const float*)d_in[14];
    const float* rfc_b1 = (const float*)d_in[15];
    const float* rfc_W2 = (const float*)d_in[16];
    const float* rfc_b2 = (const float*)d_in[17];
    const float* pfc_W1 = (const float*)d_in[18];
    const float* pfc_b1 = (const float*)d_in[19];
    const float* pfc_W2 = (const float*)d_in[20];
    const float* pfc_b2 = (const float*)d_in[21];
    float* out = (float*)d_out;

    float *GXs, *GXr, *HsA, *HsB, *HrA, *HrB;
    h16 *GXw, *Xh, *WihH, *WhhH, *WsH, *WshhH, *WrhhH, *SHiA, *SHiB;
    unsigned int* barPtr;
    cudaGetSymbolAddress((void**)&GXw, g_GXw);
    cudaGetSymbolAddress((void**)&GXs, g_GXs);
    cudaGetSymbolAddress((void**)&GXr, g_GXr);
    cudaGetSymbolAddress((void**)&HsA, g_HsA);
    cudaGetSymbolAddress((void**)&HsB, g_HsB);
    cudaGetSymbolAddress((void**)&HrA, g_HrA);
    cudaGetSymbolAddress((void**)&HrB, g_HrB);
    cudaGetSymbolAddress((void**)&Xh, g_Xh);
    cudaGetSymbolAddress((void**)&WihH, g_WihH);
    cudaGetSymbolAddress((void**)&WhhH, g_WhhH);
    cudaGetSymbolAddress((void**)&WsH, g_WsH);
    cudaGetSymbolAddress((void**)&WshhH, g_WshhH);
    cudaGetSymbolAddress((void**)&WrhhH, g_WrhhH);
    cudaGetSymbolAddress((void**)&SHiA, g_SHiA);
    cudaGetSymbolAddress((void**)&SHiB, g_SHiB);
    cudaGetSymbolAddress((void**)&barPtr, g_bar);

    const int SMEM_GEMM = 65536;
    cudaFuncSetAttribute(gemm_wmma2<h16>, cudaFuncAttributeMaxDynamicSharedMemorySize, SMEM_GEMM);
    cudaFuncSetAttribute(gemm_wmma2<float>, cudaFuncAttributeMaxDynamicSharedMemorySize, SMEM_GEMM);
    cudaFuncSetAttribute(gru_word_persistent, cudaFuncAttributeMaxDynamicSharedMemorySize, PSMEM);

    // ---- prep ----
    cudaMemsetAsync(barPtr, 0, 32 * sizeof(unsigned int));
    split_w_single<<<(GDIM * KPAD + 255) / 256, 256>>>(w_Wih, WihH, GDIM, EDIM, KPAD);
    {
        int n4 = GDIM * HDIM / 4;
        split_w_quad<<<(4 * n4 + 255) / 256, 256>>>(w_Whh, WhhH, s_Wih, WsH,
                                                    s_Whh, WshhH, r_Whh, WrhhH, n4);
    }
    gather_h16_kernel<<<(int)(((size_t)MW * KP4 + 255) / 256), 256>>>(idx, emb, Xh);

    // ---- word level: gx (fp16 out) ----
    gemm_wmma2<h16><<<dim3(GDIM / 128, MW / 128), 256, SMEM_GEMM>>>(Xh, WihH,
                                                                    w_bih, GXw, KPAD, GDIM);

    // t=0, then persistent loop t=1..31 (cooperative launch for co-residency,
    // step sync = group-local barriers)
    gru_init_h16<<<(NW * HDIM + 255) / 256, 256>>>(GXw, w_bhh, SHiA, NW, TWSTEPS);
    {
        cudaLaunchConfig_t cfg = {};
        cfg.gridDim = dim3(HDIM / 32, NW / 128);    // (8, 32) = 256 CTAs
        cfg.blockDim = dim3(256, 1, 1);
        cfg.dynamicSmemBytes = PSMEM;
        cudaLaunchAttribute attr;
        attr.id = cudaLaunchAttributeCooperative;
        attr.val.cooperative = 1;
        cfg.attrs = &attr;
        cfg.numAttrs = 1;
        cudaLaunchKernelEx(&cfg, gru_word_persistent,
                           SHiA, SHiB, (const h16*)WhhH,
                           (const float*)w_bhh, (const h16*)GXw,
                           (unsigned int*)barPtr);
    }
    h16* sent_hi = SHiB;   // 31 iterations -> B buffers

    // ---- sentence level ----
    gemm_wmma2<float><<<dim3(GDIM / 128, (NS * TSSTEPS) / 128), 256, SMEM_GEMM>>>(
        sent_hi, WsH, s_bih, GXs, HDIM, GDIM);

    gru_init_plain<<<(NS * HDIM + 255) / 256, 256>>>(GXs, s_bhh, HsA, NS, TSSTEPS);
    gru_tail_fused<4><<<NS / 4, 256>>>(HsA, WshhH, s_bhh, GXs, TSSTEPS, HsB);
    const float* p_batch = HsB;

    // r_stars -> out[16 .. 272)
    mlp_kernel<<<NS, 128>>>(p_batch, rfc_W1, rfc_b1, rfc_W2, rfc_b2, out + NR);

    // ---- review level ----
    {
        dim3 grid(GDIM / BN, (NR * TRSTEPS + BM - 1) / BM);
        sgemm_f32x2<<<grid, 256>>>(p_batch, r_Wih, r_bih, GXr, NR * TRSTEPS, HDIM, GDIM);
    }
    gru_init_plain<<<(NR * HDIM + 255) / 256, 256>>>(GXr, r_bhh, HrA, NR, TRSTEPS);
    gru_tail_fused<1><<<NR, 256>>>(HrA, WrhhH, r_bhh, GXr, TRSTEPS, HrB);

    // b_stars -> out[0 .. 16)
    mlp_kernel<<<NR, 128>>>(HrB, pfc_W1, pfc_b1, pfc_W2, pfc_b2, out);
}

// round 17
// speedup vs baseline: 1.4507x; 1.1112x over previous
#include <cuda_runtime.h>
#include <cuda_fp16.h>
#include <mma.h>
#include <cooperative_groups.h>
#include <math.h>
#include <stdint.h>

using namespace nvcuda;

// ---------------- problem dims ----------------
#define HDIM 256
#define GDIM 768
#define EDIM 200
#define NW 4096
#define TWSTEPS 32
#define NS 256
#define TSSTEPS 16
#define NR 16
#define TRSTEPS 16
#define MW (NW * TWSTEPS)
#define KPAD 224
#define KP4 (KPAD / 4)

typedef unsigned long long ull;
typedef __half h16;

// ---------------- scratch ----------------
__device__ __align__(16) h16 g_GXw[(size_t)MW * GDIM];   // fp16 word input gates
__device__ float g_GXs[(size_t)NS * TSSTEPS * GDIM];
__device__ float g_GXr[(size_t)NR * TRSTEPS * GDIM];
__device__ float g_HsA[NS * HDIM], g_HsB[NS * HDIM];
__device__ float g_HrA[NR * HDIM], g_HrB[NR * HDIM];
__device__ __align__(16) h16 g_Xh[(size_t)MW * KPAD];
__device__ __align__(16) h16 g_WihH[GDIM * KPAD];
__device__ __align__(16) h16 g_WhhH[GDIM * HDIM];
__device__ __align__(16) h16 g_WsH [GDIM * HDIM];
__device__ __align__(16) h16 g_WshhH[GDIM * HDIM];
__device__ __align__(16) h16 g_WrhhH[GDIM * HDIM];
__device__ __align__(16) h16 g_SHiA[NW * HDIM], g_SHiB[NW * HDIM];
__device__ unsigned int g_bar[32];     // per-m0-group arrival counters

// ---------------- fast transcendentals (MUFU-minimal) ----------------
__device__ __forceinline__ float sigmoid_f(float x) {
    return __fdividef(1.f, 1.f + __expf(-x));          // EX2 + RCP
}
__device__ __forceinline__ float tanh_f(float x) {
    float xc = fminf(fmaxf(x, -15.f), 15.f);
    float e = __expf(2.f * xc);                        // EX2
    return __fdividef(e - 1.f, e + 1.f);               // RCP
}

// ---------------- helpers ----------------
__device__ __forceinline__ ull pack2(float lo, float hi) {
    ull r; asm("mov.b64 %0, {%1, %2};" : "=l"(r) : "f"(lo), "f"(hi)); return r;
}
__device__ __forceinline__ ull dup2(float v) { return pack2(v, v); }
__device__ __forceinline__ void ffma2(ull& d, ull a, ull b) {
    asm("fma.rn.f32x2 %0, %1, %2, %3;" : "=l"(d) : "l"(a), "l"(b), "l"(d));
}
__device__ __forceinline__ float2 unpack2(ull v) {
    float2 f; asm("mov.b64 {%0, %1}, %2;" : "=f"(f.x), "=f"(f.y) : "l"(v)); return f;
}
__device__ __forceinline__ void cp16(uint32_t s, const void* g) {
    asm volatile("cp.async.cg.shared.global [%0], [%1], 16;" :: "r"(s), "l"(g));
}
#define CP_COMMIT() asm volatile("cp.async.commit_group;" ::: "memory")
#define CP_WAIT(n)  asm volatile("cp.async.wait_group %0;" :: "n"(n) : "memory")

__device__ __forceinline__ void ld_h4(float* o, const h16* p) {
    ull v = *reinterpret_cast<const ull*>(p);
    const h16* q = reinterpret_cast<const h16*>(&v);
    o[0] = __half2float(q[0]); o[1] = __half2float(q[1]);
    o[2] = __half2float(q[2]); o[3] = __half2float(q[3]);
}
__device__ __forceinline__ void ld_h4_cg(float* o, const h16* p) {
    ull v = __ldcg(reinterpret_cast<const ull*>(p));
    const h16* q = reinterpret_cast<const h16*>(&v);
    o[0] = __half2float(q[0]); o[1] = __half2float(q[1]);
    o[2] = __half2float(q[2]); o[3] = __half2float(q[3]);
}

// ---------------- prep kernels ----------------
__global__ void split_w_single(const float* __restrict__ src, h16* __restrict__ dst,
                               int rows, int cs, int cd)
{
    int i = blockIdx.x * blockDim.x + threadIdx.x;
    if (i >= rows * cd) return;
    int r = i / cd, c = i - r * cd;
    float v = (c < cs) ? src[(size_t)r * cs + c] : 0.f;
    dst[i] = __float2half_rn(v);
}

__global__ void split_w_quad(const float* s0, h16* d0, const float* s1, h16* d1,
                             const float* s2, h16* d2, const float* s3, h16* d3,
                             int n4)
{
    int i = blockIdx.x * blockDim.x + threadIdx.x;
    int mat = i / n4;
    int off = (i - mat * n4) * 4;
    if (mat >= 4) return;
    const float* s = (mat == 0) ? s0 : (mat == 1) ? s1 : (mat == 2) ? s2 : s3;
    h16* d = (mat == 0) ? d0 : (mat == 1) ? d1 : (mat == 2) ? d2 : d3;
    float4 v = *reinterpret_cast<const float4*>(s + off);
    h16 hb[4];
    hb[0] = __float2half_rn(v.x); hb[1] = __float2half_rn(v.y);
    hb[2] = __float2half_rn(v.z); hb[3] = __float2half_rn(v.w);
    *reinterpret_cast<ull*>(d + off) = *reinterpret_cast<ull*>(hb);
}

__global__ void gather_h16_kernel(const int* __restrict__ idx, const float* __restrict__ emb,
                                  h16* __restrict__ hi)
{
    size_t id = (size_t)blockIdx.x * blockDim.x + threadIdx.x;
    if (id >= (size_t)MW * KP4) return;
    int row = (int)(id / KP4);
    int c4 = (int)(id - (size_t)row * KP4) * 4;
    float4 v = make_float4(0.f, 0.f, 0.f, 0.f);
    if (c4 < EDIM)
        v = *reinterpret_cast<const float4*>(emb + (size_t)idx[row] * EDIM + c4);
    h16 hb[4];
    hb[0] = __float2half_rn(v.x); hb[1] = __float2half_rn(v.y);
    hb[2] = __float2half_rn(v.z); hb[3] = __float2half_rn(v.w);
    *reinterpret_cast<ull*>(hi + (size_t)row * KPAD + c4) = *reinterpret_cast<ull*>(hb);
}

// ---------------- wmma fp16 GEMM: C = A@W^T + bias (3-stage pipeline) -------
#define LDT2 40
#define TBY (128 * LDT2 * 2)
#define GEMM_BUF (2 * TBY)

template <typename OutT>
__global__ __launch_bounds__(256, 2)
void gemm_wmma2(const h16* __restrict__ Ahp, const h16* __restrict__ Whp,
                const float* __restrict__ bias, OutT* __restrict__ C,
                int K, int N)
{
    extern __shared__ __align__(128) char sm[];
    const uint32_t sbase = (uint32_t)__cvta_generic_to_shared(sm);
    float* scratch = reinterpret_cast<float*>(sm);

    const int tid = threadIdx.x;
    const int wid = tid >> 5;
    const int m0 = blockIdx.y * 128, n0 = blockIdx.x * 128;
    const int wm = wid & 3, wn = wid >> 2;

    const int lr = tid >> 1;
    const int lq = (tid & 1) * 16;

    const h16* gA = Ahp + (size_t)(m0 + lr) * K + lq;
    const h16* gB = Whp + (size_t)(n0 + lr) * K + lq;
    const uint32_t srow = lr * LDT2 * 2 + lq * 2;

    const int ntile = K / 32;

    wmma::fragment<wmma::accumulator, 16, 16, 16, float> cf[2][4];
#pragma unroll
    for (int i = 0; i < 2; i++)
#pragma unroll
        for (int j = 0; j < 4; j++) wmma::fill_fragment(cf[i][j], 0.0f);

    auto issue = [&](int it, int stg) {
        const int kk = it * 32;
        uint32_t base = sbase + stg * GEMM_BUF;
        cp16(base + srow,            gA + kk);
        cp16(base + srow + 16,       gA + kk + 8);
        cp16(base + TBY + srow,      gB + kk);
        cp16(base + TBY + srow + 16, gB + kk + 8);
    };

    issue(0, 0); CP_COMMIT();
    if (ntile > 1) { issue(1, 1); CP_COMMIT(); }

    for (int it = 0; it < ntile; it++) {
        if (it + 1 < ntile) { CP_WAIT(1); } else { CP_WAIT(0); }
        __syncthreads();
        if (it + 2 < ntile) { issue(it + 2, (it + 2) % 3); CP_COMMIT(); }

        const h16* tA = reinterpret_cast<const h16*>(sm + (it % 3) * GEMM_BUF);
        const h16* tB = tA + 128 * LDT2;

#pragma unroll
        for (int ks = 0; ks < 32; ks += 16) {
            wmma::fragment<wmma::matrix_a, 16, 16, 16, h16, wmma::row_major> ah[2];
            wmma::fragment<wmma::matrix_b, 16, 16, 16, h16, wmma::col_major> bh[4];
#pragma unroll
            for (int i = 0; i < 2; i++)
                wmma::load_matrix_sync(ah[i], tA + (wm * 32 + i * 16) * LDT2 + ks, LDT2);
#pragma unroll
            for (int j = 0; j < 4; j++)
                wmma::load_matrix_sync(bh[j], tB + (wn * 64 + j * 16) * LDT2 + ks, LDT2);
#pragma unroll
            for (int i = 0; i < 2; i++)
#pragma unroll
                for (int j = 0; j < 4; j++)
                    wmma::mma_sync(cf[i][j], ah[i], bh[j], cf[i][j]);
        }
    }
    __syncthreads();

#pragma unroll
    for (int i = 0; i < 2; i++)
#pragma unroll
        for (int j = 0; j < 4; j++)
            wmma::store_matrix_sync(&scratch[(wm * 32 + i * 16) * 128 + wn * 64 + j * 16],
                                    cf[i][j], 128, wmma::mem_row_major);
    __syncthreads();

#pragma unroll
    for (int itx = 0; itx < 16; itx++) {
        int idx4 = tid + itx * 256;
        int r = idx4 >> 5;
        int c4 = (idx4 & 31) * 4;
        float4 v = *reinterpret_cast<const float4*>(&scratch[r * 128 + c4]);
        float4 b = *reinterpret_cast<const float4*>(&bias[n0 + c4]);
        v.x += b.x; v.y += b.y; v.z += b.z; v.w += b.w;
        if constexpr (sizeof(OutT) == 4) {
            *reinterpret_cast<float4*>(&C[(size_t)(m0 + r) * N + n0 + c4]) = v;
        } else {
            h16 hb[4];
            hb[0] = __float2half_rn(v.x); hb[1] = __float2half_rn(v.y);
            hb[2] = __float2half_rn(v.z); hb[3] = __float2half_rn(v.w);
            *reinterpret_cast<ull*>(&C[(size_t)(m0 + r) * N + n0 + c4]) =
                *reinterpret_cast<ull*>(hb);
        }
    }
}

// ---------------- persistent word-recurrent loop, group-local barriers -------
#define WROWS 96
#define WLD 264
#define WBYTES (WROWS * WLD * 2)       // 50688
#define ABUF (128 * LDT2 * 2)          // 10240 per A buffer
#define PSMEM (WBYTES + 3 * ABUF)      // 81408

__global__ __launch_bounds__(256, 2)
void gru_word_persistent(h16* __restrict__ sA, h16* __restrict__ sB,
                         const h16* __restrict__ Whp,
                         const float* __restrict__ bhh, const h16* __restrict__ gx,
                         unsigned int* __restrict__ bar)
{
    extern __shared__ __align__(128) char sm[];
    const uint32_t sbase = (uint32_t)__cvta_generic_to_shared(sm);
    const h16* Wsm = reinterpret_cast<const h16*>(sm);
    float* scratch = reinterpret_cast<float*>(sm + WBYTES);

    const int tid = threadIdx.x;
    const int wid = tid >> 5;
    const int n0 = blockIdx.x * 32;
    const int m0 = blockIdx.y * 128;
    const int grp = blockIdx.y;
    const int wm = wid & 3;
    const int wn = wid >> 2;

    // ---- prologue: load W tile once ----
    for (int task = tid; task < WROWS * 32; task += 256) {
        int rt = task >> 5;
        int q = task & 31;
        int gate = rt >> 5, col = rt & 31;
        size_t srcoff = (size_t)(gate * HDIM + n0 + col) * HDIM + q * 8;
        cp16(sbase + rt * (WLD * 2) + q * 16, Whp + srcoff);
    }
    CP_COMMIT(); CP_WAIT(0);
    __syncthreads();

    const int lr = tid >> 1;
    const int lq = (tid & 1) * 16;
    const uint32_t arow = lr * (LDT2 * 2) + lq * 2;

    for (int t = 1; t < TWSTEPS; t++) {
        const int cur = (t - 1) & 1;
        const h16* Hhi  = cur ? sB : sA;
        h16*       Hout = cur ? sA : sB;

        const h16* gAh = Hhi + (size_t)(m0 + lr) * HDIM + lq;

        auto issue = [&](int it, int stg) {
            const int kk = it * 32;
            uint32_t base = sbase + WBYTES + stg * ABUF;
            cp16(base + arow,      gAh + kk);
            cp16(base + arow + 16, gAh + kk + 8);
        };

        wmma::fragment<wmma::accumulator, 16, 16, 16, float> cf[2][3];
#pragma unroll
        for (int i = 0; i < 2; i++)
#pragma unroll
            for (int j = 0; j < 3; j++) wmma::fill_fragment(cf[i][j], 0.0f);

        issue(0, 0); CP_COMMIT();
        issue(1, 1); CP_COMMIT();

        const int ntile = HDIM / 32;
        for (int it = 0; it < ntile; it++) {
            if (it + 1 < ntile) { CP_WAIT(1); } else { CP_WAIT(0); }
            __syncthreads();
            if (it + 2 < ntile) { issue(it + 2, (it + 2) % 3); CP_COMMIT(); }

            const h16* tA = reinterpret_cast<const h16*>(sm + WBYTES + (it % 3) * ABUF);
            const int kk = it * 32;

#pragma unroll
            for (int ks = 0; ks < 32; ks += 16) {
                wmma::fragment<wmma::matrix_a, 16, 16, 16, h16, wmma::row_major> ah0, ah1;
                wmma::load_matrix_sync(ah0, tA + (wm * 32) * LDT2 + ks, LDT2);
                wmma::load_matrix_sync(ah1, tA + (wm * 32 + 16) * LDT2 + ks, LDT2);
#pragma unroll
                for (int j = 0; j < 3; j++) {
                    wmma::fragment<wmma::matrix_b, 16, 16, 16, h16, wmma::col_major> bh;
                    wmma::load_matrix_sync(bh, Wsm + (wn * 48 + j * 16) * WLD + kk + ks, WLD);
                    wmma::mma_sync(cf[0][j], ah0, bh, cf[0][j]);
                    wmma::mma_sync(cf[1][j], ah1, bh, cf[1][j]);
                }
            }
        }
        __syncthreads();

        // ---- epilogue in 2 row-passes ----
#pragma unroll
        for (int p = 0; p < 2; p++) {
            __syncthreads();
            if ((wm >> 1) == p) {
#pragma unroll
                for (int i = 0; i < 2; i++)
#pragma unroll
                    for (int j = 0; j < 3; j++)
                        wmma::store_matrix_sync(
                            &scratch[((wm & 1) * 32 + i * 16) * 96 + wn * 48 + j * 16],
                            cf[i][j], 96, wmma::mem_row_major);
            }
            __syncthreads();
#pragma unroll
            for (int itx = 0; itx < 2; itx++) {
                int task = tid + itx * 256;
                int r = task >> 3;
                int c4 = (task & 7) * 4;
                const int row = m0 + p * 64 + r;
                const int j = n0 + c4;
                const float* srow2 = &scratch[r * 96];
                float gr[4], gz[4], gn[4];
                *reinterpret_cast<float4*>(gr) = *reinterpret_cast<const float4*>(srow2 + c4);
                *reinterpret_cast<float4*>(gz) = *reinterpret_cast<const float4*>(srow2 + 32 + c4);
                *reinterpret_cast<float4*>(gn) = *reinterpret_cast<const float4*>(srow2 + 64 + c4);
                float br[4], bz[4], bn[4], xr[4], xz[4], xn[4], hh[4];
                *reinterpret_cast<float4*>(br) = *reinterpret_cast<const float4*>(bhh + j);
                *reinterpret_cast<float4*>(bz) = *reinterpret_cast<const float4*>(bhh + HDIM + j);
                *reinterpret_cast<float4*>(bn) = *reinterpret_cast<const float4*>(bhh + 2 * HDIM + j);
                const h16* gxp = gx + ((size_t)row * TWSTEPS + t) * GDIM;
                ld_h4(xr, gxp + j);
                ld_h4(xz, gxp + HDIM + j);
                ld_h4(xn, gxp + 2 * HDIM + j);
                ld_h4_cg(hh, Hhi + (size_t)row * HDIM + j);
                h16 hb[4];
#pragma unroll
                for (int u = 0; u < 4; u++) {
                    float rr = sigmoid_f(xr[u] + gr[u] + br[u]);
                    float zz = sigmoid_f(xz[u] + gz[u] + bz[u]);
                    float nv = tanh_f(xn[u] + rr * (gn[u] + bn[u]));
                    float h = (1.f - zz) * nv + zz * hh[u];
                    hb[u] = __float2half_rn(h);
                }
                *reinterpret_cast<ull*>(Hout + (size_t)row * HDIM + j) =
                    *reinterpret_cast<ull*>(hb);
            }
        }
        __syncthreads();

        // ---- group-local step barrier (8 CTAs sharing m0) ----
        if (t + 1 < TWSTEPS) {
            if (tid == 0) {
                __threadfence();
                atomicAdd(&bar[grp], 1u);
                const unsigned int target = 8u * (unsigned int)t;
                while (atomicAdd(&bar[grp], 0u) < target) {}
            }
            __syncthreads();
        }
    }
}

// ---------------- t=0 GRU steps ----------------
__global__ void gru_init_h16(const h16* __restrict__ gx, const float* __restrict__ bhh,
                             h16* __restrict__ hi, int Mseq, int T)
{
    int i = blockIdx.x * blockDim.x + threadIdx.x;
    if (i >= Mseq * HDIM) return;
    int seq = i >> 8, j = i & 255;
    const h16* g = gx + (size_t)seq * T * GDIM;
    float xr = __half2float(g[j]);
    float xz = __half2float(g[j + HDIM]);
    float xn = __half2float(g[j + 2 * HDIM]);
    float r = sigmoid_f(xr + bhh[j]);
    float z = sigmoid_f(xz + bhh[j + HDIM]);
    float n = tanh_f(xn + r * bhh[j + 2 * HDIM]);
    hi[i] = __float2half_rn((1.f - z) * n);
}

__global__ void gru_init_plain(const float* __restrict__ gx, const float* __restrict__ bhh,
                               float* __restrict__ hout, int Mseq, int T)
{
    int i = blockIdx.x * blockDim.x + threadIdx.x;
    if (i >= Mseq * HDIM) return;
    int seq = i >> 8, j = i & 255;
    const float* g = gx + (size_t)seq * T * GDIM;
    float r = sigmoid_f(g[j] + bhh[j]);
    float z = sigmoid_f(g[j + HDIM] + bhh[j + HDIM]);
    float n = tanh_f(g[j + 2 * HDIM] + r * bhh[j + 2 * HDIM]);
    hout[i] = (1.f - z) * n;
}

// ---------------- fused multi-step GRU tail ----------------------------------
template <int NSEQ>
__global__ __launch_bounds__(256)
void gru_tail_fused(const float* __restrict__ h0, const h16* __restrict__ W16,
                    const float* __restrict__ bhh, const float* __restrict__ gx,
                    int T, float* __restrict__ hfinal)
{
    __shared__ float hs[HDIM][NSEQ];
    const int tid = threadIdx.x;
    const int seq0 = blockIdx.x * NSEQ;

    for (int i = tid; i < NSEQ * HDIM; i += 256) {
        int s = i / HDIM, k = i - s * HDIM;
        hs[k][s] = h0[(size_t)(seq0 + s) * HDIM + k];
    }
    __syncthreads();

    const int j = tid;
    const h16* wr = W16 + (size_t)j * HDIM;
    const h16* wz = W16 + (size_t)(HDIM + j) * HDIM;
    const h16* wn_ = W16 + (size_t)(2 * HDIM + j) * HDIM;
    const float br = bhh[j], bz = bhh[HDIM + j], bn = bhh[2 * HDIM + j];

    for (int t = 1; t < T; t++) {
        float ar[NSEQ], az[NSEQ], an[NSEQ];
#pragma unroll
        for (int s = 0; s < NSEQ; s++) { ar[s] = 0.f; az[s] = 0.f; an[s] = 0.f; }

#pragma unroll 4
        for (int k = 0; k < HDIM; k += 8) {
            uint4 vr = *reinterpret_cast<const uint4*>(wr + k);
            uint4 vz = *reinterpret_cast<const uint4*>(wz + k);
            uint4 vn = *reinterpret_cast<const uint4*>(wn_ + k);
            const h16* pr = reinterpret_cast<const h16*>(&vr);
            const h16* pz = reinterpret_cast<const h16*>(&vz);
            const h16* pn = reinterpret_cast<const h16*>(&vn);
#pragma unroll
            for (int u = 0; u < 8; u++) {
                float fr = __half2float(pr[u]);
                float fz = __half2float(pz[u]);
                float fn = __half2float(pn[u]);
#pragma unroll
                for (int s = 0; s < NSEQ; s++) {
                    float hv = hs[k + u][s];
                    ar[s] = fmaf(fr, hv, ar[s]);
                    az[s] = fmaf(fz, hv, az[s]);
                    an[s] = fmaf(fn, hv, an[s]);
                }
            }
        }
        __syncthreads();

        float hnew[NSEQ];
#pragma unroll
        for (int s = 0; s < NSEQ; s++) {
            const float* gxp = gx + ((size_t)(seq0 + s) * T + t) * GDIM;
            float r = sigmoid_f(gxp[j] + ar[s] + br);
            float z = sigmoid_f(gxp[HDIM + j] + az[s] + bz);
            float n = tanh_f(gxp[2 * HDIM + j] + r * (an[s] + bn));
            hnew[s] = (1.f - z) * n + z * hs[j][s];
        }
#pragma unroll
        for (int s = 0; s < NSEQ; s++) hs[j][s] = hnew[s];
        __syncthreads();
    }

    for (int i = tid; i < NSEQ * HDIM; i += 256) {
        int s = i / HDIM, k = i - s * HDIM;
        hfinal[(size_t)(seq0 + s) * HDIM + k] = hs[k][s];
    }
}

// ---------------- fp32 SGEMM (review gx) ----------------
#define BM 128
#define BN 128
#define BK 8
__global__ __launch_bounds__(256, 2)
void sgemm_f32x2(const float* __restrict__ A, const float* __restrict__ W,
                 const float* __restrict__ bias, float* __restrict__ C,
                 int M, int K, int N)
{
    __shared__ float As[2][BK][BM];
    __shared__ float Bs[2][BK][BN];
    const int tid = threadIdx.x;
    const int m0 = blockIdx.y * BM;
    const int n0 = blockIdx.x * BN;
    const int a_m = tid & 127, a_kq = tid >> 7;
    const int b_n = tid >> 1,  b_kq = tid & 1;
    const bool a_valid = (m0 + a_m) < M;
    const float* Arow = A + (size_t)(a_valid ? (m0 + a_m) : 0) * K;
    const float* Brow = W + (size_t)(n0 + b_n) * K;
    const int tx = tid & 15, ty = tid >> 4;

    ull acc2[8][4];
#pragma unroll
    for (int i = 0; i < 8; i++)
#pragma unroll
        for (int j = 0; j < 4; j++) acc2[i][j] = 0ull;

    float4 av = make_float4(0.f, 0.f, 0.f, 0.f);
    if (a_valid) av = *reinterpret_cast<const float4*>(Arow + a_kq * 4);
    float4 bv = *reinterpret_cast<const float4*>(Brow + b_kq * 4);
    As[0][a_kq * 4 + 0][a_m] = av.x;  As[0][a_kq * 4 + 1][a_m] = av.y;
    As[0][a_kq * 4 + 2][a_m] = av.z;  As[0][a_kq * 4 + 3][a_m] = av.w;
    Bs[0][b_kq * 4 + 0][b_n] = bv.x;  Bs[0][b_kq * 4 + 1][b_n] = bv.y;
    Bs[0][b_kq * 4 + 2][b_n] = bv.z;  Bs[0][b_kq * 4 + 3][b_n] = bv.w;
    __syncthreads();

    int buf = 0;
    for (int kk = 0; kk < K; kk += BK) {
        const bool has_next = (kk + BK) < K;
        if (has_next) {
            if (a_valid) av = *reinterpret_cast<const float4*>(Arow + kk + BK + a_kq * 4);
            bv = *reinterpret_cast<const float4*>(Brow + kk + BK + b_kq * 4);
        }
#pragma unroll
        for (int k = 0; k < BK; k++) {
            float4 a0 = *reinterpret_cast<const float4*>(&As[buf][k][ty * 8]);
            float4 a1 = *reinterpret_cast<const float4*>(&As[buf][k][ty * 8 + 4]);
            ulonglong2 bq0 = *reinterpret_cast<const ulonglong2*>(&Bs[buf][k][tx * 8]);
            ulonglong2 bq1 = *reinterpret_cast<const ulonglong2*>(&Bs[buf][k][tx * 8 + 4]);
            ull bp[4] = {bq0.x, bq0.y, bq1.x, bq1.y};
            float a[8] = {a0.x, a0.y, a0.z, a0.w, a1.x, a1.y, a1.z, a1.w};
#pragma unroll
            for (int i = 0; i < 8; i++) {
                ull ad = dup2(a[i]);
#pragma unroll
                for (int j = 0; j < 4; j++) ffma2(acc2[i][j], ad, bp[j]);
            }
        }
        if (has_next) {
            int nb = buf ^ 1;
            As[nb][a_kq * 4 + 0][a_m] = av.x;  As[nb][a_kq * 4 + 1][a_m] = av.y;
            As[nb][a_kq * 4 + 2][a_m] = av.z;  As[nb][a_kq * 4 + 3][a_m] = av.w;
            Bs[nb][b_kq * 4 + 0][b_n] = bv.x;  Bs[nb][b_kq * 4 + 1][b_n] = bv.y;
            Bs[nb][b_kq * 4 + 2][b_n] = bv.z;  Bs[nb][b_kq * 4 + 3][b_n] = bv.w;
            __syncthreads();
            buf = nb;
        }
    }
#pragma unroll
    for (int i = 0; i < 8; i++) {
        int row = m0 + ty * 8 + i;
        if (row >= M) continue;
#pragma unroll
        for (int j = 0; j < 4; j++) {
            int col = n0 + tx * 8 + j * 2;
            float2 p = unpack2(acc2[i][j]);
            float2 bb = *reinterpret_cast<const float2*>(bias + col);
            float2 o; o.x = p.x + bb.x; o.y = p.y + bb.y;
            *reinterpret_cast<float2*>(C + (size_t)row * N + col) = o;
        }
    }
}

// ---------------- MLP ----------------
__global__ __launch_bounds__(128)
void mlp_kernel(const float* __restrict__ X,
                const float* __restrict__ W1, const float* __restrict__ b1,
                const float* __restrict__ W2, const float* __restrict__ b2,
                float* __restrict__ out)
{
    const int row = blockIdx.x;
    const int i = threadIdx.x;
    __shared__ float xs[HDIM];
    __shared__ float red[4];
    xs[i]       = X[(size_t)row * HDIM + i];
    xs[i + 128] = X[(size_t)row * HDIM + i + 128];
    __syncthreads();
    const float* w = W1 + (size_t)i * HDIM;
    float acc = b1[i];
#pragma unroll 8
    for (int k = 0; k < HDIM; k += 4) {
        float4 wv = *reinterpret_cast<const float4*>(w + k);
        acc = fmaf(wv.x, xs[k], acc);
        acc = fmaf(wv.y, xs[k + 1], acc);
        acc = fmaf(wv.z, xs[k + 2], acc);
        acc = fmaf(wv.w, xs[k + 3], acc);
    }
    const float scale = 1.0507009873554805f;
    const float alpha = 1.6732632423543772f;
    float s = scale * (acc > 0.f ? acc : alpha * (__expf(acc) - 1.f));
    float v = s * W2[i];
#pragma unroll
    for (int off = 16; off > 0; off >>= 1)
        v += __shfl_down_sync(0xffffffffu, v, off);
    if ((i & 31) == 0) red[i >> 5] = v;
    __syncthreads();
    if (i == 0) out[row] = red[0] + red[1] + red[2] + red[3] + b2[0];
}

// ---------------- host orchestration ----------------
extern "C" void kernel_launch(void* const* d_in, const int* in_sizes, int n_in,
                              void* d_out, int out_size)
{
    (void)in_sizes; (void)n_in; (void)out_size;

    const int*   idx    = (const int*)  d_in[0];
    const float* emb    = (const float*)d_in[1];
    const float* w_Wih  = (const float*)d_in[2];
    const float* w_Whh  = (const float*)d_in[3];
    const float* w_bih  = (const float*)d_in[4];
    const float* w_bhh  = (const float*)d_in[5];
    const float* s_Wih  = (const float*)d_in[6];
    const float* s_Whh  = (const float*)d_in[7];
    const float* s_bih  = (const float*)d_in[8];
    const float* s_bhh  = (const float*)d_in[9];
    const float* r_Wih  = (const float*)d_in[10];
    const float* r_Whh  = (const float*)d_in[11];
    const float* r_bih  = (const float*)d_in[12];
    const float* r_bhh  = (const float*)d_in[13];
    const float* rfc_W1 = (const float*)d_in[14];
    const float* rfc_b1 = (const float*)d_in[15];
    const float* rfc_W2 = (const float*)d_in[16];
    const float* rfc_b2 = (const float*)d_in[17];
    const float* pfc_W1 = (const float*)d_in[18];
    const float* pfc_b1 = (const float*)d_in[19];
    const float* pfc_W2 = (const float*)d_in[20];
    const float* pfc_b2 = (const float*)d_in[21];
    float* out = (float*)d_out;

    float *GXs, *GXr, *HsA, *HsB, *HrA, *HrB;
    h16 *GXw, *Xh, *WihH, *WhhH, *WsH, *WshhH, *WrhhH, *SHiA, *SHiB;
    unsigned int* barPtr;
    cudaGetSymbolAddress((void**)&GXw, g_GXw);
    cudaGetSymbolAddress((void**)&GXs, g_GXs);
    cudaGetSymbolAddress((void**)&GXr, g_GXr);
    cudaGetSymbolAddress((void**)&HsA, g_HsA);
    cudaGetSymbolAddress((void**)&HsB, g_HsB);
    cudaGetSymbolAddress((void**)&HrA, g_HrA);
    cudaGetSymbolAddress((void**)&HrB, g_HrB);
    cudaGetSymbolAddress((void**)&Xh, g_Xh);
    cudaGetSymbolAddress((void**)&WihH, g_WihH);
    cudaGetSymbolAddress((void**)&WhhH, g_WhhH);
    cudaGetSymbolAddress((void**)&WsH, g_WsH);
    cudaGetSymbolAddress((void**)&WshhH, g_WshhH);
    cudaGetSymbolAddress((void**)&WrhhH, g_WrhhH);
    cudaGetSymbolAddress((void**)&SHiA, g_SHiA);
    cudaGetSymbolAddress((void**)&SHiB, g_SHiB);
    cudaGetSymbolAddress((void**)&barPtr, g_bar);

    const int SMEM_GEMM = 65536;
    cudaFuncSetAttribute(gemm_wmma2<h16>, cudaFuncAttributeMaxDynamicSharedMemorySize, SMEM_GEMM);
    cudaFuncSetAttribute(gemm_wmma2<float>, cudaFuncAttributeMaxDynamicSharedMemorySize, SMEM_GEMM);
    cudaFuncSetAttribute(gru_word_persistent, cudaFuncAttributeMaxDynamicSharedMemorySize, PSMEM);

    // ---- prep ----
    cudaMemsetAsync(barPtr, 0, 32 * sizeof(unsigned int));
    split_w_single<<<(GDIM * KPAD + 255) / 256, 256>>>(w_Wih, WihH, GDIM, EDIM, KPAD);
    {
        int n4 = GDIM * HDIM / 4;
        split_w_quad<<<(4 * n4 + 255) / 256, 256>>>(w_Whh, WhhH, s_Wih, WsH,
                                                    s_Whh, WshhH, r_Whh, WrhhH, n4);
    }
    gather_h16_kernel<<<(int)(((size_t)MW * KP4 + 255) / 256), 256>>>(idx, emb, Xh);

    // ---- word level: gx (fp16 out) ----
    gemm_wmma2<h16><<<dim3(GDIM / 128, MW / 128), 256, SMEM_GEMM>>>(Xh, WihH,
                                                                    w_bih, GXw, KPAD, GDIM);

    // t=0, then persistent loop t=1..31
    gru_init_h16<<<(NW * HDIM + 255) / 256, 256>>>(GXw, w_bhh, SHiA, NW, TWSTEPS);
    {
        cudaLaunchConfig_t cfg = {};
        cfg.gridDim = dim3(HDIM / 32, NW / 128);    // (8, 32) = 256 CTAs
        cfg.blockDim = dim3(256, 1, 1);
        cfg.dynamicSmemBytes = PSMEM;
        cudaLaunchAttribute attr;
        attr.id = cudaLaunchAttributeCooperative;
        attr.val.cooperative = 1;
        cfg.attrs = &attr;
        cfg.numAttrs = 1;
        cudaLaunchKernelEx(&cfg, gru_word_persistent,
                           SHiA, SHiB, (const h16*)WhhH,
                           (const float*)w_bhh, (const h16*)GXw,
                           (unsigned int*)barPtr);
    }
    h16* sent_hi = SHiB;   // 31 iterations -> B buffers

    // ---- sentence level ----
    gemm_wmma2<float><<<dim3(GDIM / 128, (NS * TSSTEPS) / 128), 256, SMEM_GEMM>>>(
        sent_hi, WsH, s_bih, GXs, HDIM, GDIM);

    gru_init_plain<<<(NS * HDIM + 255) / 256, 256>>>(GXs, s_bhh, HsA, NS, TSSTEPS);
    gru_tail_fused<4><<<NS / 4, 256>>>(HsA, WshhH, s_bhh, GXs, TSSTEPS, HsB);
    const float* p_batch = HsB;

    // r_stars -> out[16 .. 272)
    mlp_kernel<<<NS, 128>>>(p_batch, rfc_W1, rfc_b1, rfc_W2, rfc_b2, out + NR);

    // ---- review level ----
    {
        dim3 grid(GDIM / BN, (NR * TRSTEPS + BM - 1) / BM);
        sgemm_f32x2<<<grid, 256>>>(p_batch, r_Wih, r_bih, GXr, NR * TRSTEPS, HDIM, GDIM);
    }
    gru_init_plain<<<(NR * HDIM + 255) / 256, 256>>>(GXr, r_bhh, HrA, NR, TRSTEPS);
    gru_tail_fused<1><<<NR, 256>>>(HrA, WrhhH, r_bhh, GXr, TRSTEPS, HrB);

    // b_stars -> out[0 .. 16)
    mlp_kernel<<<NR, 128>>>(HrB, pfc_W1, pfc_b1, pfc_W2, pfc_b2, out);
}